// round 14
// baseline (speedup 1.0000x reference)
#include <cuda_runtime.h>
#include <cuda_fp16.h>
#include <math.h>
#include <stdint.h>

#define B_   16
#define C_   384
#define S_   784
#define NH_  6
#define HD_  64
#define NBI  9
#define NPART 256          // 16 batches * 16 spatial tiles
#define NTOK (B_*S_)       // 12544

// ---------------- scratch (static device globals; no allocation) ------------
__device__ unsigned short g_dw  [(size_t)NBI*NTOK*C_]; // fp16 bits of conv out [bi][tok][c]
__device__ unsigned short g_qkv [(size_t)NBI*NTOK*C_]; // fp16 [bi][b][h][s][d] (q pre-scaled by scale*log2e)
__device__ float          g_M   [NBI*C_*C_];           // combined lin@pw (fp32, for bias)
__device__ unsigned short g_Mt  [NBI*C_*C_];           // fp16 of M * a (gemm B operand)
__device__ float          g_psum[NBI*C_*NPART];
__device__ float          g_psq [NBI*C_*NPART];
__device__ float          g_a   [NBI*C_];
__device__ float          g_bc  [NBI*C_];
__device__ float          g_bias[NBI*C_];

// ---------------- helpers ---------------------------------------------------
__device__ __forceinline__ float ex2f(float x) {
    float r;
    asm("ex2.approx.f32 %0, %1;" : "=f"(r) : "f"(x));
    return r;
}

__device__ __forceinline__ uint32_t pack_h2(float lo, float hi) {
    uint32_t r;
    asm("cvt.rn.f16x2.f32 %0, %1, %2;" : "=r"(r) : "f"(hi), "f"(lo));  // 2nd src -> low half
    return r;
}

__device__ __forceinline__ void mma_f16(float c[4], const uint32_t a[4],
                                        uint32_t b0, uint32_t b1) {
    asm volatile(
        "mma.sync.aligned.m16n8k16.row.col.f32.f16.f16.f32 "
        "{%0,%1,%2,%3}, {%4,%5,%6,%7}, {%8,%9}, {%0,%1,%2,%3};\n"
        : "+f"(c[0]), "+f"(c[1]), "+f"(c[2]), "+f"(c[3])
        : "r"(a[0]), "r"(a[1]), "r"(a[2]), "r"(a[3]), "r"(b0), "r"(b1));
}

__device__ __forceinline__ void ldsm4t(uint32_t& r0, uint32_t& r1, uint32_t& r2,
                                       uint32_t& r3, uint32_t addr) {
    asm volatile("ldmatrix.sync.aligned.m8n8.x4.trans.shared.b16 {%0,%1,%2,%3}, [%4];"
        : "=r"(r0), "=r"(r1), "=r"(r2), "=r"(r3) : "r"(addr));
}

__device__ __forceinline__ uint32_t smem_u32(const void* p) {
    uint32_t a;
    asm("{ .reg .u64 t; cvta.to.shared.u64 t, %1; cvt.u32.u64 %0, t; }"
        : "=r"(a) : "l"(p));
    return a;
}

#define CP_A16(dst, src) \
    asm volatile("cp.async.ca.shared.global [%0], [%1], 16;\n" \
                 :: "r"(dst), "l"(src) : "memory")
#define CP_A16P(dst, src, ok) \
    asm volatile("cp.async.ca.shared.global [%0], [%1], 16, %2;\n" \
                 :: "r"(dst), "l"(src), "r"((ok) ? 16 : 0) : "memory")
#define CP_COMMIT() asm volatile("cp.async.commit_group;\n" ::: "memory")
#define CP_WAIT(n)  asm volatile("cp.async.wait_group %0;\n" :: "n"(n) : "memory")

// scale * log2e = 384^-0.5 * 1.4426950408889634
#define QSCALE 0.07362222f

// ---------------- 1) depthwise 3x3 conv (q,k,v fused) + BN partial stats ----
__global__ void dw_kernel(const float* __restrict__ x1, const float* __restrict__ x2,
                          const float* __restrict__ dww) {
    int c    = threadIdx.x;
    int tile = blockIdx.x;
    int b    = blockIdx.y;
    int br   = blockIdx.z;

    float w[3][9];
#pragma unroll
    for (int j = 0; j < 3; j++)
#pragma unroll
        for (int k = 0; k < 9; k++)
            w[j][k] = dww[((3*br+j)*C_ + c)*9 + k];

    const float* X1 = x1 + (size_t)b*S_*C_;
    const float* X2 = x2 + (size_t)b*S_*C_;
    unsigned short* out0 = g_dw + ((size_t)(3*br+0)*B_ + b)*(size_t)S_*C_;
    unsigned short* out1 = g_dw + ((size_t)(3*br+1)*B_ + b)*(size_t)S_*C_;
    unsigned short* out2 = g_dw + ((size_t)(3*br+2)*B_ + b)*(size_t)S_*C_;

    float sum[3] = {0.f,0.f,0.f}, sq[3] = {0.f,0.f,0.f};
    int s0 = tile*49;
    int y = s0 / 28, x = s0 - y*28;
    for (int i = 0; i < 49; i++) {
        int s = s0 + i;
        float a0 = 0.f, a1 = 0.f, a2 = 0.f;
#pragma unroll
        for (int ky = 0; ky < 3; ky++) {
            int yy = y + ky - 1;
            if (yy < 0 || yy >= 28) continue;
#pragma unroll
            for (int kx = 0; kx < 3; kx++) {
                int xx = x + kx - 1;
                if (xx < 0 || xx >= 28) continue;
                int sn = yy*28 + xx;
                float v;
                if      (br == 0) v = X1[sn*C_ + c];
                else if (br == 1) v = X2[sn*C_ + c];
                else              v = X1[sn*C_ + c] + X2[sn*C_ + c];
                int kk = ky*3 + kx;
                a0 += w[0][kk]*v;  a1 += w[1][kk]*v;  a2 += w[2][kk]*v;
            }
        }
        out0[s*C_ + c] = __half_as_ushort(__float2half_rn(a0));
        out1[s*C_ + c] = __half_as_ushort(__float2half_rn(a1));
        out2[s*C_ + c] = __half_as_ushort(__float2half_rn(a2));
        sum[0] += a0;  sq[0] += a0*a0;
        sum[1] += a1;  sq[1] += a1*a1;
        sum[2] += a2;  sq[2] += a2*a2;
        if (++x == 28) { x = 0; y++; }
    }
    int p = b*16 + tile;
#pragma unroll
    for (int j = 0; j < 3; j++) {
        int bi = 3*br + j;
        g_psum[(bi*C_ + c)*NPART + p] = sum[j];
        g_psq [(bi*C_ + c)*NPART + p] = sq[j];
    }
}

// ---------------- 2) finalize BN stats (warp per channel) -------------------
__global__ void stats_kernel(const float* __restrict__ gamma, const float* __restrict__ beta) {
    int gw   = (blockIdx.x*256 + threadIdx.x) >> 5;
    int lane = threadIdx.x & 31;
    if (gw >= NBI*C_) return;
    const float* ps = g_psum + (size_t)gw*NPART;
    const float* pq = g_psq  + (size_t)gw*NPART;
    double s = 0.0, q = 0.0;
#pragma unroll
    for (int i = 0; i < NPART/32; i++) { s += ps[lane + i*32]; q += pq[lane + i*32]; }
#pragma unroll
    for (int o = 16; o > 0; o >>= 1) {
        s += __shfl_xor_sync(0xffffffffu, s, o);
        q += __shfl_xor_sync(0xffffffffu, q, o);
    }
    if (lane == 0) {
        const double N = (double)(B_*S_);
        float mu  = (float)(s / N);
        float var = (float)(q / N - (s/N)*(s/N));
        float a   = gamma[gw] * rsqrtf(var + 1e-5f);
        g_a [gw] = a;
        g_bc[gw] = beta[gw] - mu*a;
    }
}

// ---------------- 3) fold: M[bi] = lin[li] @ pw[bi]; Mt = fp16(M*a) ---------
__global__ void __launch_bounds__(256) fold_kernel(const float* __restrict__ pw,
                                                   const float* __restrict__ lin) {
    int bi = blockIdx.z;
    int br = bi / 3, j = bi - 3*br;
    int li = (br == 2 ? 3 : 3*br) + j;      // branch-3 reuses branch-2 lin weights
    const float* L = lin + (size_t)li*C_*C_;
    const float* P = pw  + (size_t)bi*C_*C_;

    __shared__ float As[16][65];
    __shared__ float Bs[16][65];
    int t  = threadIdx.x;
    int tx = t & 15, ty = t >> 4;
    int obase = blockIdx.y*64, cbase = blockIdx.x*64;
    float acc[4][4] = {};

    for (int k0 = 0; k0 < C_; k0 += 16) {
#pragma unroll
        for (int e = 0; e < 4; e++) {
            int idx = t + e*256;
            int kk = idx & 15, oo = idx >> 4;
            As[kk][oo] = L[(obase+oo)*C_ + k0 + kk];
        }
#pragma unroll
        for (int e = 0; e < 4; e++) {
            int cc = t & 63, kk = (t >> 6) + e*4;
            Bs[kk][cc] = P[(k0+kk)*C_ + cbase + cc];
        }
        __syncthreads();
#pragma unroll
        for (int kk = 0; kk < 16; kk++) {
            float ar[4], brr[4];
#pragma unroll
            for (int i = 0; i < 4; i++) ar[i]  = As[kk][ty*4+i];
#pragma unroll
            for (int jj = 0; jj < 4; jj++) brr[jj] = Bs[kk][tx*4+jj];
#pragma unroll
            for (int i = 0; i < 4; i++)
#pragma unroll
                for (int jj = 0; jj < 4; jj++) acc[i][jj] += ar[i]*brr[jj];
        }
        __syncthreads();
    }
    float*          Mo = g_M  + (size_t)bi*C_*C_;
    unsigned short* Mt = g_Mt + (size_t)bi*C_*C_;
#pragma unroll
    for (int i = 0; i < 4; i++)
#pragma unroll
        for (int jj = 0; jj < 4; jj++) {
            int oo = obase + ty*4 + i, cc = cbase + tx*4 + jj;
            Mo[oo*C_ + cc] = acc[i][jj];
            Mt[oo*C_ + cc] = __half_as_ushort(__float2half_rn(acc[i][jj] * g_a[bi*C_ + cc]));
        }
}

// ---------------- 4) combined bias (warp per output) ------------------------
__global__ void bias_kernel(const float* __restrict__ lin, const float* __restrict__ pwb) {
    int gw   = (blockIdx.x*256 + threadIdx.x) >> 5;
    int lane = threadIdx.x & 31;
    if (gw >= NBI*C_) return;
    int bi = gw / C_, o = gw - bi*C_;
    int brr = bi/3, j = bi - 3*brr;
    int li = (brr == 2 ? 3 : 3*brr) + j;
    const float* L    = lin + ((size_t)li*C_ + o)*C_;
    const float* Pb   = pwb + (size_t)bi*C_;
    const float* Mrow = g_M + ((size_t)bi*C_ + o)*C_;
    const float* bc   = g_bc + (size_t)bi*C_;
    float s = 0.f;
    for (int k = lane; k < C_; k += 32) s += L[k]*Pb[k] + Mrow[k]*bc[k];
#pragma unroll
    for (int off = 16; off > 0; off >>= 1) s += __shfl_xor_sync(0xffffffffu, s, off);
    if (lane == 0) g_bias[gw] = s;
}

// ---------------- 5) main GEMM (fp16 m16n8k16, cp.async 2-stage) ------------
// heads = dw @ (M*a)^T + bias; q tensors (bi%3==0) pre-scaled by scale*log2e.
// Block 128x128, BK=64 halves (32 u32/row), 6 kt iters. Smem 65536 B.
// Swizzle: 16B-chunk c of row r stored at c^(r&7).
__global__ void __launch_bounds__(256) gemm_kernel() {
    extern __shared__ uint32_t gsm[];
    uint32_t sb = smem_u32(gsm);
    // u32 offsets: As0 @0, As1 @4096, Bs0 @8192, Bs1 @12288

    int bi    = blockIdx.z;
    int rbase = blockIdx.y * 128;
    int obase = blockIdx.x * 128;
    const unsigned short* Ag = g_dw + (size_t)bi*NTOK*C_;
    const unsigned short* Bg = g_Mt + (size_t)bi*C_*C_;
    float qs = (bi % 3 == 0) ? QSCALE : 1.0f;

    int t    = threadIdx.x;
    int wid  = t >> 5, lane = t & 31;
    int wm   = wid >> 1, wn = wid & 1;
    int lr   = lane >> 2, lc = lane & 3;

    float acc[2][8][4] = {};

    // prologue: stage 0 (each tile: 128 rows x 8 chunks of 16B)
    {
        uint32_t ab = sb, bb = sb + 8192u*4u;
#pragma unroll
        for (int e = 0; e < 4; e++) {
            int i = e*256 + t;
            int r = i >> 3, ch = i & 7;
            uint32_t dsto = (uint32_t)(r*32 + ((ch ^ (r&7)) << 2))*4u;
            CP_A16(ab + dsto, Ag + (size_t)(rbase+r)*C_ + ch*8);
            CP_A16(bb + dsto, Bg + (size_t)(obase+r)*C_ + ch*8);
        }
        CP_COMMIT();
    }

    for (int kt = 0; kt < 6; kt++) {
        __syncthreads();                         // prev MMA done; next stage free
        if (kt < 5) {
            int kbase = (kt+1)*64;               // in halves
            uint32_t st = (uint32_t)((kt+1) & 1);
            uint32_t ab = sb + st*4096u*4u;
            uint32_t bb = sb + (8192u + st*4096u)*4u;
#pragma unroll
            for (int e = 0; e < 4; e++) {
                int i = e*256 + t;
                int r = i >> 3, ch = i & 7;
                uint32_t dsto = (uint32_t)(r*32 + ((ch ^ (r&7)) << 2))*4u;
                CP_A16(ab + dsto, Ag + (size_t)(rbase+r)*C_ + kbase + ch*8);
                CP_A16(bb + dsto, Bg + (size_t)(obase+r)*C_ + kbase + ch*8);
            }
        }
        CP_COMMIT();
        CP_WAIT(1);
        __syncthreads();                         // stage kt ready & visible

        const uint32_t* As = gsm + (kt & 1)*4096;
        const uint32_t* Bs = gsm + 8192 + (kt & 1)*4096;
#pragma unroll
        for (int ks = 0; ks < 4; ks++) {
            int cl  = ((2*ks    ) ^ lr)*4 + lc;
            int chh = ((2*ks + 1) ^ lr)*4 + lc;
            uint32_t af[2][4];
#pragma unroll
            for (int i = 0; i < 2; i++) {
                int r = wm*32 + i*16;
                af[i][0] = As[(r + lr    )*32 + cl ];
                af[i][1] = As[(r + lr + 8)*32 + cl ];
                af[i][2] = As[(r + lr    )*32 + chh];
                af[i][3] = As[(r + lr + 8)*32 + chh];
            }
#pragma unroll
            for (int j = 0; j < 8; j++) {
                int n = wn*64 + j*8;
                uint32_t b0 = Bs[(n + lr)*32 + cl ];
                uint32_t b1 = Bs[(n + lr)*32 + chh];
#pragma unroll
                for (int i = 0; i < 2; i++) mma_f16(acc[i][j], af[i], b0, b1);
            }
        }
    }

    // epilogue: fp16 bits of (acc + bias)*qs into [bi][b][h][s][d]
    const float* bias = g_bias + (size_t)bi*C_;
#pragma unroll
    for (int i = 0; i < 2; i++) {
        int r0 = rbase + wm*32 + i*16 + lr;
        int r1 = r0 + 8;
        int b0r = r0 / S_, s0r = r0 - b0r*S_;
        int b1r = r1 / S_, s1r = r1 - b1r*S_;
#pragma unroll
        for (int j = 0; j < 8; j++) {
            int o = obase + wn*64 + j*8 + 2*lc;   // even
            int h = o >> 6, d = o & 63;
            float bo0 = bias[o], bo1 = bias[o+1];
            uint32_t* d0 = (uint32_t*)(g_qkv + ((((size_t)bi*B_ + b0r)*NH_ + h)*S_ + s0r)*HD_ + d);
            *d0 = pack_h2((acc[i][j][0] + bo0) * qs, (acc[i][j][1] + bo1) * qs);
            uint32_t* d1 = (uint32_t*)(g_qkv + ((((size_t)bi*B_ + b1r)*NH_ + h)*S_ + s1r)*HD_ + d);
            *d1 = pack_h2((acc[i][j][2] + bo0) * qs, (acc[i][j][3] + bo1) * qs);
        }
    }
}

// ---------------- 6) flash attention (fp16 mma, cp.async pipeline) ----------
// 256 thr / 8 warps, TQ=128, TK=64, head dim 64 (= one fp16 row of 128B).
// Smem 40960 B: Q/P 128x32u32, K 2x 64x32, V 64x32 (all 16B-chunk swizzled).
// QK B-frags: direct u32 LDS (d-pairs adjacent). PV B-frags: ldmatrix.x4.trans.
// q pre-scaled by scale*log2e; softmax via ex2.approx; mask only on kt==12.
__global__ void __launch_bounds__(256, 2) attn_kernel(float* __restrict__ out) {
    extern __shared__ uint32_t smem[];
    uint32_t* sm_q = smem;               // 128*32 u32 (Q, then P)
    uint32_t* sm_k = smem + 4096;        // 2 x 64*32
    uint32_t sb   = smem_u32(smem);
    uint32_t sb_q = sb;
    uint32_t sb_k = sb + 4096u*4u;
    uint32_t sb_v = sb + 8192u*4u;       // 64*32

    int t    = threadIdx.x;
    int wid  = t >> 5, lane = t & 31;
    int lr   = lane >> 2, lc = lane & 3;
    int qt   = blockIdx.x;               // 7 q-tiles of 128
    int bh   = blockIdx.y;
    int br   = blockIdx.z;
    int b = bh / NH_, h = bh - b*NH_;

    const unsigned short* Qg = g_qkv + (((size_t)(3*br+0)*B_ + b)*NH_ + h)*(size_t)S_*HD_;
    const unsigned short* Kg = g_qkv + (((size_t)(3*br+1)*B_ + b)*NH_ + h)*(size_t)S_*HD_;
    const unsigned short* Vg = g_qkv + (((size_t)(3*br+2)*B_ + b)*NH_ + h)*(size_t)S_*HD_;
    float* Op = out + ((size_t)br*B_ + b)*(size_t)S_*C_ + (size_t)h*S_*HD_;

    int q0 = qt*128;

    // prologue: async Q (128 rows x 8 chunks), then K(0)
#pragma unroll
    for (int e = 0; e < 4; e++) {
        int i = e*256 + t;
        int q = i >> 3, ch = i & 7;
        int qg = q0 + q;
        const unsigned short* src = Qg + (size_t)(qg < S_ ? qg : S_-1)*HD_ + ch*8;
        CP_A16P(sb_q + (uint32_t)(q*32 + ((ch ^ (q&7)) << 2))*4u, src, qg < S_);
    }
    CP_COMMIT();
#pragma unroll
    for (int e = 0; e < 2; e++) {
        int i = e*256 + t;
        int k = i >> 3, ch = i & 7;
        CP_A16(sb_k + (uint32_t)(k*32 + ((ch ^ (k&7)) << 2))*4u, Kg + (size_t)k*HD_ + ch*8);
    }
    CP_COMMIT();
    CP_WAIT(1);            // Q ready
    __syncthreads();

    // hoist Q A-frags (warp w owns rows 16w..16w+15)
    int r = wid * 16;
    uint32_t qa[4][4];
#pragma unroll
    for (int ks = 0; ks < 4; ks++) {
        int cl  = ((2*ks    ) ^ lr)*4 + lc;
        int chh = ((2*ks + 1) ^ lr)*4 + lc;
        qa[ks][0] = sm_q[(r+lr  )*32 + cl ];
        qa[ks][1] = sm_q[(r+lr+8)*32 + cl ];
        qa[ks][2] = sm_q[(r+lr  )*32 + chh];
        qa[ks][3] = sm_q[(r+lr+8)*32 + chh];
    }

    // lane constants for ldmatrix V addressing
    int krow  = ((lane >> 3) & 1)*8 + (lane & 7);   // row within 16-k chunk
    int clnof = lane >> 4;                          // 0/1: chunk pair selector
    int swz7  = lane & 7;                           // = krow&7

    float ov[8][4] = {};
    float m0 = -1e30f, m1 = -1e30f, l0 = 0.f, l1 = 0.f;

    for (int kt = 0; kt < 13; kt++) {
        __syncthreads();        // (A) PV(kt-1) done: V free, K[(kt+1)&1] free, P consumed

        // issue V(kt)
        int k0 = kt*64;
#pragma unroll
        for (int e = 0; e < 2; e++) {
            int i = e*256 + t;
            int k = i >> 3, ch = i & 7;
            int kg = k0 + k;
            const unsigned short* src = Vg + (size_t)(kg < S_ ? kg : S_-1)*HD_ + ch*8;
            CP_A16P(sb_v + (uint32_t)(k*32 + ((ch ^ (k&7)) << 2))*4u, src, kg < S_);
        }
        CP_COMMIT();
        // issue K(kt+1)
        if (kt < 12) {
            int kn = (kt+1)*64;
            uint32_t kb = sb_k + (uint32_t)((kt+1) & 1)*8192u;
#pragma unroll
            for (int e = 0; e < 2; e++) {
                int i = e*256 + t;
                int k = i >> 3, ch = i & 7;
                int kg = kn + k;
                const unsigned short* src = Kg + (size_t)(kg < S_ ? kg : S_-1)*HD_ + ch*8;
                CP_A16P(kb + (uint32_t)(k*32 + ((ch ^ (k&7)) << 2))*4u, src, kg < S_);
            }
        }
        CP_COMMIT();
        CP_WAIT(2);             // K(kt) complete
        __syncthreads();        // (B) K(kt) visible

        const uint32_t* Ks_ = sm_k + (kt & 1)*2048;

        // ---- scores: S[16q x 64k] per warp (log2 units) ----
        float sc[8][4] = {};
#pragma unroll
        for (int ks = 0; ks < 4; ks++) {
            int cl  = ((2*ks    ) ^ lr)*4 + lc;
            int chh = ((2*ks + 1) ^ lr)*4 + lc;
#pragma unroll
            for (int j = 0; j < 8; j++) {
                uint32_t b0 = Ks_[(8*j+lr)*32 + cl ];
                uint32_t b1 = Ks_[(8*j+lr)*32 + chh];
                mma_f16(sc[j], qa[ks], b0, b1);
            }
        }

        // ---- masking: only last k-tile ----
        if (kt == 12) {
#pragma unroll
            for (int j = 0; j < 8; j++) {
                int col = 768 + 8*j + 2*lc;
                if (col     >= S_) { sc[j][0] = -1e30f; sc[j][2] = -1e30f; }
                if (col + 1 >= S_) { sc[j][1] = -1e30f; sc[j][3] = -1e30f; }
            }
        }

        // ---- online softmax, log2 domain ----
        float mx0 = -1e30f, mx1 = -1e30f;
#pragma unroll
        for (int j = 0; j < 8; j++) {
            mx0 = fmaxf(mx0, fmaxf(sc[j][0], sc[j][1]));
            mx1 = fmaxf(mx1, fmaxf(sc[j][2], sc[j][3]));
        }
        mx0 = fmaxf(mx0, __shfl_xor_sync(0xffffffffu, mx0, 1));
        mx0 = fmaxf(mx0, __shfl_xor_sync(0xffffffffu, mx0, 2));
        mx1 = fmaxf(mx1, __shfl_xor_sync(0xffffffffu, mx1, 1));
        mx1 = fmaxf(mx1, __shfl_xor_sync(0xffffffffu, mx1, 2));
        float mn0 = fmaxf(m0, mx0), mn1 = fmaxf(m1, mx1);
        float a0  = ex2f(m0 - mn0), a1 = ex2f(m1 - mn1);
        float rs0 = 0.f, rs1 = 0.f;
#pragma unroll
        for (int j = 0; j < 8; j++) {
            sc[j][0] = ex2f(sc[j][0] - mn0); rs0 += sc[j][0];
            sc[j][1] = ex2f(sc[j][1] - mn0); rs0 += sc[j][1];
            sc[j][2] = ex2f(sc[j][2] - mn1); rs1 += sc[j][2];
            sc[j][3] = ex2f(sc[j][3] - mn1); rs1 += sc[j][3];
        }
        rs0 += __shfl_xor_sync(0xffffffffu, rs0, 1);
        rs0 += __shfl_xor_sync(0xffffffffu, rs0, 2);
        rs1 += __shfl_xor_sync(0xffffffffu, rs1, 1);
        rs1 += __shfl_xor_sync(0xffffffffu, rs1, 2);
        l0 = l0*a0 + rs0;  l1 = l1*a1 + rs1;
        m0 = mn0;          m1 = mn1;
#pragma unroll
        for (int j = 0; j < 8; j++) {
            ov[j][0] *= a0; ov[j][1] *= a0;
            ov[j][2] *= a1; ov[j][3] *= a1;
        }

        // ---- store P into Q buffer (fp16 pairs, same swizzle) ----
#pragma unroll
        for (int j = 0; j < 8; j++) {
            int pos = ((j ^ lr) << 2) | lc;     // ci=4j+lc swizzled
            sm_q[(r+lr  )*32 + pos] = pack_h2(sc[j][0], sc[j][1]);
            sm_q[(r+lr+8)*32 + pos] = pack_h2(sc[j][2], sc[j][3]);
        }
        CP_WAIT(1);             // V(kt) complete
        __syncthreads();        // (C) P + V visible

        // ---- PV: O[16q x 64d] += P @ V (B-frags via ldmatrix.trans) ----
#pragma unroll
        for (int ks = 0; ks < 4; ks++) {
            int cl  = ((2*ks    ) ^ lr)*4 + lc;
            int chh = ((2*ks + 1) ^ lr)*4 + lc;
            uint32_t pa[4];
            pa[0] = sm_q[(r+lr  )*32 + cl ];
            pa[1] = sm_q[(r+lr+8)*32 + cl ];
            pa[2] = sm_q[(r+lr  )*32 + chh];
            pa[3] = sm_q[(r+lr+8)*32 + chh];
            uint32_t vrow = sb_v + (uint32_t)((16*ks + krow)*32)*4u;
#pragma unroll
            for (int jp = 0; jp < 4; jp++) {
                int chv = (2*jp + clnof) ^ swz7;
                uint32_t v0, v1, v2, v3;
                ldsm4t(v0, v1, v2, v3, vrow + (uint32_t)(chv << 4));
                mma_f16(ov[2*jp    ], pa, v0, v1);
                mma_f16(ov[2*jp + 1], pa, v2, v3);
            }
        }
    }

    float inv0 = 1.0f / l0, inv1 = 1.0f / l1;
    int qq0 = q0 + r + lr, qq1 = qq0 + 8;
#pragma unroll
    for (int j = 0; j < 8; j++) {
        int d = 8*j + 2*lc;
        if (qq0 < S_) {
            float2 o2 = make_float2(ov[j][0]*inv0, ov[j][1]*inv0);
            *(float2*)&Op[(size_t)qq0*HD_ + d] = o2;
        }
        if (qq1 < S_) {
            float2 o2 = make_float2(ov[j][2]*inv1, ov[j][3]*inv1);
            *(float2*)&Op[(size_t)qq1*HD_ + d] = o2;
        }
    }
}

// ---------------------------------------------------------------------------
extern "C" void kernel_launch(void* const* d_in, const int* in_sizes, int n_in,
                              void* d_out, int out_size) {
    // metadata order: x1, h1, w1, x2, h2, w2, dw_w, bn_gamma, bn_beta, pw_w, pw_b, lin_w
    const float* x1  = (const float*)d_in[0];
    const float* x2  = (const float*)d_in[3];
    const float* dww = (const float*)d_in[6];
    const float* gam = (const float*)d_in[7];
    const float* bet = (const float*)d_in[8];
    const float* pw  = (const float*)d_in[9];
    const float* pwb = (const float*)d_in[10];
    const float* lin = (const float*)d_in[11];
    float* out = (float*)d_out;

    cudaFuncSetAttribute(gemm_kernel, cudaFuncAttributeMaxDynamicSharedMemorySize, 65536);
    cudaFuncSetAttribute(attn_kernel, cudaFuncAttributeMaxDynamicSharedMemorySize, 40960);

    dw_kernel   <<<dim3(16, 16, 3), 384>>>(x1, x2, dww);
    stats_kernel<<<(NBI*C_*32 + 255)/256, 256>>>(gam, bet);
    fold_kernel <<<dim3(6, 6, 9), 256>>>(pw, lin);
    bias_kernel <<<(NBI*C_*32 + 255)/256, 256>>>(lin, pwb);
    gemm_kernel <<<dim3(3, 98, 9), 256, 65536>>>();
    attn_kernel <<<dim3(7, 96, 3), 256, 40960>>>(out);
}

// round 15
// speedup vs baseline: 1.4208x; 1.4208x over previous
#include <cuda_runtime.h>
#include <cuda_fp16.h>
#include <math.h>
#include <stdint.h>

#define B_   16
#define C_   384
#define S_   784
#define NH_  6
#define HD_  64
#define NBI  9
#define NPART 256          // 16 batches * 16 spatial tiles
#define NTOK (B_*S_)       // 12544

// ---------------- scratch (static device globals; no allocation) ------------
__device__ unsigned short g_dw  [(size_t)NBI*NTOK*C_]; // fp16 bits of conv out [bi][tok][c]
__device__ unsigned short g_qkv [(size_t)NBI*NTOK*C_]; // fp16 [bi][b][h][s][d] (q pre-scaled by scale*log2e)
__device__ float          g_M   [NBI*C_*C_];           // combined lin@pw (fp32, for bias)
__device__ unsigned short g_Mt  [NBI*C_*C_];           // fp16 of M * a (gemm B operand)
__device__ float          g_psum[NBI*C_*NPART];
__device__ float          g_psq [NBI*C_*NPART];
__device__ float          g_a   [NBI*C_];
__device__ float          g_bc  [NBI*C_];
__device__ float          g_bias[NBI*C_];

// ---------------- helpers ---------------------------------------------------
__device__ __forceinline__ float ex2f(float x) {
    float r;
    asm("ex2.approx.f32 %0, %1;" : "=f"(r) : "f"(x));
    return r;
}

__device__ __forceinline__ uint32_t pack_h2(float lo, float hi) {
    uint32_t r;
    asm("cvt.rn.f16x2.f32 %0, %1, %2;" : "=r"(r) : "f"(hi), "f"(lo));  // 2nd src -> low half
    return r;
}

__device__ __forceinline__ void mma_f16(float c[4], const uint32_t a[4],
                                        uint32_t b0, uint32_t b1) {
    asm volatile(
        "mma.sync.aligned.m16n8k16.row.col.f32.f16.f16.f32 "
        "{%0,%1,%2,%3}, {%4,%5,%6,%7}, {%8,%9}, {%0,%1,%2,%3};\n"
        : "+f"(c[0]), "+f"(c[1]), "+f"(c[2]), "+f"(c[3])
        : "r"(a[0]), "r"(a[1]), "r"(a[2]), "r"(a[3]), "r"(b0), "r"(b1));
}

__device__ __forceinline__ void ldsm4t(uint32_t& r0, uint32_t& r1, uint32_t& r2,
                                       uint32_t& r3, uint32_t addr) {
    asm volatile("ldmatrix.sync.aligned.m8n8.x4.trans.shared.b16 {%0,%1,%2,%3}, [%4];"
        : "=r"(r0), "=r"(r1), "=r"(r2), "=r"(r3) : "r"(addr));
}

__device__ __forceinline__ uint32_t smem_u32(const void* p) {
    uint32_t a;
    asm("{ .reg .u64 t; cvta.to.shared.u64 t, %1; cvt.u32.u64 %0, t; }"
        : "=r"(a) : "l"(p));
    return a;
}

#define CP_A16(dst, src) \
    asm volatile("cp.async.ca.shared.global [%0], [%1], 16;\n" \
                 :: "r"(dst), "l"(src) : "memory")
#define CP_A16P(dst, src, ok) \
    asm volatile("cp.async.ca.shared.global [%0], [%1], 16, %2;\n" \
                 :: "r"(dst), "l"(src), "r"((ok) ? 16 : 0) : "memory")
#define CP_COMMIT() asm volatile("cp.async.commit_group;\n" ::: "memory")
#define CP_WAIT(n)  asm volatile("cp.async.wait_group %0;\n" :: "n"(n) : "memory")

// scale * log2e = 384^-0.5 * 1.4426950408889634
#define QSCALE 0.07362222f

// ---------------- 1) depthwise 3x3 conv (q,k,v fused) + BN partial stats ----
__global__ void dw_kernel(const float* __restrict__ x1, const float* __restrict__ x2,
                          const float* __restrict__ dww) {
    int c    = threadIdx.x;
    int tile = blockIdx.x;
    int b    = blockIdx.y;
    int br   = blockIdx.z;

    float w[3][9];
#pragma unroll
    for (int j = 0; j < 3; j++)
#pragma unroll
        for (int k = 0; k < 9; k++)
            w[j][k] = dww[((3*br+j)*C_ + c)*9 + k];

    const float* X1 = x1 + (size_t)b*S_*C_;
    const float* X2 = x2 + (size_t)b*S_*C_;
    unsigned short* out0 = g_dw + ((size_t)(3*br+0)*B_ + b)*(size_t)S_*C_;
    unsigned short* out1 = g_dw + ((size_t)(3*br+1)*B_ + b)*(size_t)S_*C_;
    unsigned short* out2 = g_dw + ((size_t)(3*br+2)*B_ + b)*(size_t)S_*C_;

    float sum[3] = {0.f,0.f,0.f}, sq[3] = {0.f,0.f,0.f};
    int s0 = tile*49;
    int y = s0 / 28, x = s0 - y*28;
    for (int i = 0; i < 49; i++) {
        int s = s0 + i;
        float a0 = 0.f, a1 = 0.f, a2 = 0.f;
#pragma unroll
        for (int ky = 0; ky < 3; ky++) {
            int yy = y + ky - 1;
            if (yy < 0 || yy >= 28) continue;
#pragma unroll
            for (int kx = 0; kx < 3; kx++) {
                int xx = x + kx - 1;
                if (xx < 0 || xx >= 28) continue;
                int sn = yy*28 + xx;
                float v;
                if      (br == 0) v = X1[sn*C_ + c];
                else if (br == 1) v = X2[sn*C_ + c];
                else              v = X1[sn*C_ + c] + X2[sn*C_ + c];
                int kk = ky*3 + kx;
                a0 += w[0][kk]*v;  a1 += w[1][kk]*v;  a2 += w[2][kk]*v;
            }
        }
        out0[s*C_ + c] = __half_as_ushort(__float2half_rn(a0));
        out1[s*C_ + c] = __half_as_ushort(__float2half_rn(a1));
        out2[s*C_ + c] = __half_as_ushort(__float2half_rn(a2));
        sum[0] += a0;  sq[0] += a0*a0;
        sum[1] += a1;  sq[1] += a1*a1;
        sum[2] += a2;  sq[2] += a2*a2;
        if (++x == 28) { x = 0; y++; }
    }
    int p = b*16 + tile;
#pragma unroll
    for (int j = 0; j < 3; j++) {
        int bi = 3*br + j;
        g_psum[(bi*C_ + c)*NPART + p] = sum[j];
        g_psq [(bi*C_ + c)*NPART + p] = sq[j];
    }
}

// ---------------- 2) fold: BN stats (absorbed) + M = lin@pw; Mt = fp16(M*a) -
// Each block first computes BN stats for its 64 cbase channels (identical
// lane-strided double reduction as the old stats_kernel -> bit-identical).
// Redundant across blockIdx.y (same values, deterministic). Also publishes
// g_a/g_bc for bias_kernel.
__global__ void __launch_bounds__(256) fold_kernel(const float* __restrict__ pw,
                                                   const float* __restrict__ lin,
                                                   const float* __restrict__ gamma,
                                                   const float* __restrict__ beta) {
    __shared__ float s_a[64], s_bc[64];

    int bi = blockIdx.z;
    int br = bi / 3, j = bi - 3*br;
    int li = (br == 2 ? 3 : 3*br) + j;      // branch-3 reuses branch-2 lin weights
    const float* L = lin + (size_t)li*C_*C_;
    const float* P = pw  + (size_t)bi*C_*C_;

    int t  = threadIdx.x;
    int tx = t & 15, ty = t >> 4;
    int wid = t >> 5, lane = t & 31;
    int obase = blockIdx.y*64, cbase = blockIdx.x*64;

    // ---- BN stats for channels [cbase, cbase+64): warp per channel ----
    for (int cw = wid; cw < 64; cw += 8) {
        int gwc = bi*C_ + cbase + cw;
        const float* ps = g_psum + (size_t)gwc*NPART;
        const float* pq = g_psq  + (size_t)gwc*NPART;
        double s = 0.0, q = 0.0;
#pragma unroll
        for (int i = 0; i < NPART/32; i++) { s += ps[lane + i*32]; q += pq[lane + i*32]; }
#pragma unroll
        for (int o = 16; o > 0; o >>= 1) {
            s += __shfl_xor_sync(0xffffffffu, s, o);
            q += __shfl_xor_sync(0xffffffffu, q, o);
        }
        if (lane == 0) {
            const double N = (double)(B_*S_);
            float mu  = (float)(s / N);
            float var = (float)(q / N - (s/N)*(s/N));
            float a   = gamma[gwc] * rsqrtf(var + 1e-5f);
            float bc  = beta[gwc] - mu*a;
            s_a [cw] = a;   s_bc[cw] = bc;
            g_a [gwc] = a;  g_bc[gwc] = bc;     // for bias_kernel
        }
    }
    // (first __syncthreads below orders s_a/s_bc before any epilogue read)

    __shared__ float As[16][65];
    __shared__ float Bs[16][65];
    float acc[4][4] = {};

    for (int k0 = 0; k0 < C_; k0 += 16) {
#pragma unroll
        for (int e = 0; e < 4; e++) {
            int idx = t + e*256;
            int kk = idx & 15, oo = idx >> 4;
            As[kk][oo] = L[(obase+oo)*C_ + k0 + kk];
        }
#pragma unroll
        for (int e = 0; e < 4; e++) {
            int cc = t & 63, kk = (t >> 6) + e*4;
            Bs[kk][cc] = P[(k0+kk)*C_ + cbase + cc];
        }
        __syncthreads();
#pragma unroll
        for (int kk = 0; kk < 16; kk++) {
            float ar[4], brr[4];
#pragma unroll
            for (int i = 0; i < 4; i++) ar[i]  = As[kk][ty*4+i];
#pragma unroll
            for (int jj = 0; jj < 4; jj++) brr[jj] = Bs[kk][tx*4+jj];
#pragma unroll
            for (int i = 0; i < 4; i++)
#pragma unroll
                for (int jj = 0; jj < 4; jj++) acc[i][jj] += ar[i]*brr[jj];
        }
        __syncthreads();
    }
    float*          Mo = g_M  + (size_t)bi*C_*C_;
    unsigned short* Mt = g_Mt + (size_t)bi*C_*C_;
#pragma unroll
    for (int i = 0; i < 4; i++)
#pragma unroll
        for (int jj = 0; jj < 4; jj++) {
            int oo = obase + ty*4 + i, ci = tx*4 + jj, cc = cbase + ci;
            Mo[oo*C_ + cc] = acc[i][jj];
            Mt[oo*C_ + cc] = __half_as_ushort(__float2half_rn(acc[i][jj] * s_a[ci]));
        }
}

// ---------------- 3) combined bias (warp per output) ------------------------
__global__ void bias_kernel(const float* __restrict__ lin, const float* __restrict__ pwb) {
    int gw   = (blockIdx.x*256 + threadIdx.x) >> 5;
    int lane = threadIdx.x & 31;
    if (gw >= NBI*C_) return;
    int bi = gw / C_, o = gw - bi*C_;
    int brr = bi/3, j = bi - 3*brr;
    int li = (brr == 2 ? 3 : 3*brr) + j;
    const float* L    = lin + ((size_t)li*C_ + o)*C_;
    const float* Pb   = pwb + (size_t)bi*C_;
    const float* Mrow = g_M + ((size_t)bi*C_ + o)*C_;
    const float* bc   = g_bc + (size_t)bi*C_;
    float s = 0.f;
    for (int k = lane; k < C_; k += 32) s += L[k]*Pb[k] + Mrow[k]*bc[k];
#pragma unroll
    for (int off = 16; off > 0; off >>= 1) s += __shfl_xor_sync(0xffffffffu, s, off);
    if (lane == 0) g_bias[gw] = s;
}

// ---------------- 4) main GEMM (fp16 m16n8k16, cp.async 2-stage) ------------
// heads = dw @ (M*a)^T + bias; q tensors (bi%3==0) pre-scaled by scale*log2e.
// Block 128x128, BK=64 halves (32 u32/row), 6 kt iters. Smem 65536 B.
// Swizzle: 16B-chunk c of row r stored at c^(r&7).
__global__ void __launch_bounds__(256) gemm_kernel() {
    extern __shared__ uint32_t gsm[];
    uint32_t sb = smem_u32(gsm);
    // u32 offsets: As0 @0, As1 @4096, Bs0 @8192, Bs1 @12288

    int bi    = blockIdx.z;
    int rbase = blockIdx.y * 128;
    int obase = blockIdx.x * 128;
    const unsigned short* Ag = g_dw + (size_t)bi*NTOK*C_;
    const unsigned short* Bg = g_Mt + (size_t)bi*C_*C_;
    float qs = (bi % 3 == 0) ? QSCALE : 1.0f;

    int t    = threadIdx.x;
    int wid  = t >> 5, lane = t & 31;
    int wm   = wid >> 1, wn = wid & 1;
    int lr   = lane >> 2, lc = lane & 3;

    float acc[2][8][4] = {};

    // prologue: stage 0 (each tile: 128 rows x 8 chunks of 16B)
    {
        uint32_t ab = sb, bb = sb + 8192u*4u;
#pragma unroll
        for (int e = 0; e < 4; e++) {
            int i = e*256 + t;
            int r = i >> 3, ch = i & 7;
            uint32_t dsto = (uint32_t)(r*32 + ((ch ^ (r&7)) << 2))*4u;
            CP_A16(ab + dsto, Ag + (size_t)(rbase+r)*C_ + ch*8);
            CP_A16(bb + dsto, Bg + (size_t)(obase+r)*C_ + ch*8);
        }
        CP_COMMIT();
    }

    for (int kt = 0; kt < 6; kt++) {
        __syncthreads();                         // prev MMA done; next stage free
        if (kt < 5) {
            int kbase = (kt+1)*64;               // in halves
            uint32_t st = (uint32_t)((kt+1) & 1);
            uint32_t ab = sb + st*4096u*4u;
            uint32_t bb = sb + (8192u + st*4096u)*4u;
#pragma unroll
            for (int e = 0; e < 4; e++) {
                int i = e*256 + t;
                int r = i >> 3, ch = i & 7;
                uint32_t dsto = (uint32_t)(r*32 + ((ch ^ (r&7)) << 2))*4u;
                CP_A16(ab + dsto, Ag + (size_t)(rbase+r)*C_ + kbase + ch*8);
                CP_A16(bb + dsto, Bg + (size_t)(obase+r)*C_ + kbase + ch*8);
            }
        }
        CP_COMMIT();
        CP_WAIT(1);
        __syncthreads();                         // stage kt ready & visible

        const uint32_t* As = gsm + (kt & 1)*4096;
        const uint32_t* Bs = gsm + 8192 + (kt & 1)*4096;
#pragma unroll
        for (int ks = 0; ks < 4; ks++) {
            int cl  = ((2*ks    ) ^ lr)*4 + lc;
            int chh = ((2*ks + 1) ^ lr)*4 + lc;
            uint32_t af[2][4];
#pragma unroll
            for (int i = 0; i < 2; i++) {
                int r = wm*32 + i*16;
                af[i][0] = As[(r + lr    )*32 + cl ];
                af[i][1] = As[(r + lr + 8)*32 + cl ];
                af[i][2] = As[(r + lr    )*32 + chh];
                af[i][3] = As[(r + lr + 8)*32 + chh];
            }
#pragma unroll
            for (int j = 0; j < 8; j++) {
                int n = wn*64 + j*8;
                uint32_t b0 = Bs[(n + lr)*32 + cl ];
                uint32_t b1 = Bs[(n + lr)*32 + chh];
#pragma unroll
                for (int i = 0; i < 2; i++) mma_f16(acc[i][j], af[i], b0, b1);
            }
        }
    }

    // epilogue: fp16 bits of (acc + bias)*qs into [bi][b][h][s][d]
    const float* bias = g_bias + (size_t)bi*C_;
#pragma unroll
    for (int i = 0; i < 2; i++) {
        int r0 = rbase + wm*32 + i*16 + lr;
        int r1 = r0 + 8;
        int b0r = r0 / S_, s0r = r0 - b0r*S_;
        int b1r = r1 / S_, s1r = r1 - b1r*S_;
#pragma unroll
        for (int j = 0; j < 8; j++) {
            int o = obase + wn*64 + j*8 + 2*lc;   // even
            int h = o >> 6, d = o & 63;
            float bo0 = bias[o], bo1 = bias[o+1];
            uint32_t* d0 = (uint32_t*)(g_qkv + ((((size_t)bi*B_ + b0r)*NH_ + h)*S_ + s0r)*HD_ + d);
            *d0 = pack_h2((acc[i][j][0] + bo0) * qs, (acc[i][j][1] + bo1) * qs);
            uint32_t* d1 = (uint32_t*)(g_qkv + ((((size_t)bi*B_ + b1r)*NH_ + h)*S_ + s1r)*HD_ + d);
            *d1 = pack_h2((acc[i][j][2] + bo0) * qs, (acc[i][j][3] + bo1) * qs);
        }
    }
}

// ---------------- 5) flash attention (fp16 mma, cp.async pipeline) ----------
// 128 thr / 4 warps, TQ=64, TK=64 -> 32 KB smem, <=128 regs => 4 blocks/SM
// (4 independent barrier domains vs 2 lockstep ones). Per-warp code identical
// to the TQ=128 version. All loaders cover full 512-chunk tiles (e<4 @128thr).
__global__ void __launch_bounds__(128, 4) attn_kernel(float* __restrict__ out) {
    extern __shared__ uint32_t smem[];
    uint32_t* sm_q = smem;               // 64*32 u32 (Q, then P)
    uint32_t* sm_k = smem + 2048;        // 2 x 64*32
    uint32_t sb   = smem_u32(smem);
    uint32_t sb_q = sb;
    uint32_t sb_k = sb + 2048u*4u;
    uint32_t sb_v = sb + 6144u*4u;       // 64*32

    int t    = threadIdx.x;
    int wid  = t >> 5, lane = t & 31;
    int lr   = lane >> 2, lc = lane & 3;
    int qt   = blockIdx.x;               // 13 q-tiles of 64
    int bh   = blockIdx.y;
    int br   = blockIdx.z;
    int b = bh / NH_, h = bh - b*NH_;

    const unsigned short* Qg = g_qkv + (((size_t)(3*br+0)*B_ + b)*NH_ + h)*(size_t)S_*HD_;
    const unsigned short* Kg = g_qkv + (((size_t)(3*br+1)*B_ + b)*NH_ + h)*(size_t)S_*HD_;
    const unsigned short* Vg = g_qkv + (((size_t)(3*br+2)*B_ + b)*NH_ + h)*(size_t)S_*HD_;
    float* Op = out + ((size_t)br*B_ + b)*(size_t)S_*C_ + (size_t)h*S_*HD_;

    int q0 = qt*64;

    // prologue: async Q (64 rows x 8 chunks = 512), then K(0) (512 chunks)
#pragma unroll
    for (int e = 0; e < 4; e++) {
        int i = e*128 + t;
        int q = i >> 3, ch = i & 7;
        int qg = q0 + q;
        const unsigned short* src = Qg + (size_t)(qg < S_ ? qg : S_-1)*HD_ + ch*8;
        CP_A16P(sb_q + (uint32_t)(q*32 + ((ch ^ (q&7)) << 2))*4u, src, qg < S_);
    }
    CP_COMMIT();
#pragma unroll
    for (int e = 0; e < 4; e++) {
        int i = e*128 + t;
        int k = i >> 3, ch = i & 7;
        CP_A16(sb_k + (uint32_t)(k*32 + ((ch ^ (k&7)) << 2))*4u, Kg + (size_t)k*HD_ + ch*8);
    }
    CP_COMMIT();
    CP_WAIT(1);            // Q ready
    __syncthreads();

    // hoist Q A-frags (warp w owns rows 16w..16w+15)
    int r = wid * 16;
    uint32_t qa[4][4];
#pragma unroll
    for (int ks = 0; ks < 4; ks++) {
        int cl  = ((2*ks    ) ^ lr)*4 + lc;
        int chh = ((2*ks + 1) ^ lr)*4 + lc;
        qa[ks][0] = sm_q[(r+lr  )*32 + cl ];
        qa[ks][1] = sm_q[(r+lr+8)*32 + cl ];
        qa[ks][2] = sm_q[(r+lr  )*32 + chh];
        qa[ks][3] = sm_q[(r+lr+8)*32 + chh];
    }

    // lane constants for ldmatrix V addressing
    int krow  = ((lane >> 3) & 1)*8 + (lane & 7);   // row within 16-k chunk
    int clnof = lane >> 4;                          // 0/1: chunk pair selector
    int swz7  = lane & 7;                           // = krow&7

    float ov[8][4] = {};
    float m0 = -1e30f, m1 = -1e30f, l0 = 0.f, l1 = 0.f;

    for (int kt = 0; kt < 13; kt++) {
        __syncthreads();        // (A) PV(kt-1) done: V free, K[(kt+1)&1] free, P consumed

        // issue V(kt) (512 chunks)
        int k0 = kt*64;
#pragma unroll
        for (int e = 0; e < 4; e++) {
            int i = e*128 + t;
            int k = i >> 3, ch = i & 7;
            int kg = k0 + k;
            const unsigned short* src = Vg + (size_t)(kg < S_ ? kg : S_-1)*HD_ + ch*8;
            CP_A16P(sb_v + (uint32_t)(k*32 + ((ch ^ (k&7)) << 2))*4u, src, kg < S_);
        }
        CP_COMMIT();
        // issue K(kt+1)
        if (kt < 12) {
            int kn = (kt+1)*64;
            uint32_t kb = sb_k + (uint32_t)((kt+1) & 1)*8192u;
#pragma unroll
            for (int e = 0; e < 4; e++) {
                int i = e*128 + t;
                int k = i >> 3, ch = i & 7;
                int kg = kn + k;
                const unsigned short* src = Kg + (size_t)(kg < S_ ? kg : S_-1)*HD_ + ch*8;
                CP_A16P(kb + (uint32_t)(k*32 + ((ch ^ (k&7)) << 2))*4u, src, kg < S_);
            }
        }
        CP_COMMIT();
        CP_WAIT(2);             // K(kt) complete
        __syncthreads();        // (B) K(kt) visible

        const uint32_t* Ks_ = sm_k + (kt & 1)*2048;

        // ---- scores: S[16q x 64k] per warp (log2 units) ----
        float sc[8][4] = {};
#pragma unroll
        for (int ks = 0; ks < 4; ks++) {
            int cl  = ((2*ks    ) ^ lr)*4 + lc;
            int chh = ((2*ks + 1) ^ lr)*4 + lc;
#pragma unroll
            for (int j = 0; j < 8; j++) {
                uint32_t b0 = Ks_[(8*j+lr)*32 + cl ];
                uint32_t b1 = Ks_[(8*j+lr)*32 + chh];
                mma_f16(sc[j], qa[ks], b0, b1);
            }
        }

        // ---- masking: only last k-tile ----
        if (kt == 12) {
#pragma unroll
            for (int j = 0; j < 8; j++) {
                int col = 768 + 8*j + 2*lc;
                if (col     >= S_) { sc[j][0] = -1e30f; sc[j][2] = -1e30f; }
                if (col + 1 >= S_) { sc[j][1] = -1e30f; sc[j][3] = -1e30f; }
            }
        }

        // ---- online softmax, log2 domain ----
        float mx0 = -1e30f, mx1 = -1e30f;
#pragma unroll
        for (int j = 0; j < 8; j++) {
            mx0 = fmaxf(mx0, fmaxf(sc[j][0], sc[j][1]));
            mx1 = fmaxf(mx1, fmaxf(sc[j][2], sc[j][3]));
        }
        mx0 = fmaxf(mx0, __shfl_xor_sync(0xffffffffu, mx0, 1));
        mx0 = fmaxf(mx0, __shfl_xor_sync(0xffffffffu, mx0, 2));
        mx1 = fmaxf(mx1, __shfl_xor_sync(0xffffffffu, mx1, 1));
        mx1 = fmaxf(mx1, __shfl_xor_sync(0xffffffffu, mx1, 2));
        float mn0 = fmaxf(m0, mx0), mn1 = fmaxf(m1, mx1);
        float a0  = ex2f(m0 - mn0), a1 = ex2f(m1 - mn1);
        float rs0 = 0.f, rs1 = 0.f;
#pragma unroll
        for (int j = 0; j < 8; j++) {
            sc[j][0] = ex2f(sc[j][0] - mn0); rs0 += sc[j][0];
            sc[j][1] = ex2f(sc[j][1] - mn0); rs0 += sc[j][1];
            sc[j][2] = ex2f(sc[j][2] - mn1); rs1 += sc[j][2];
            sc[j][3] = ex2f(sc[j][3] - mn1); rs1 += sc[j][3];
        }
        rs0 += __shfl_xor_sync(0xffffffffu, rs0, 1);
        rs0 += __shfl_xor_sync(0xffffffffu, rs0, 2);
        rs1 += __shfl_xor_sync(0xffffffffu, rs1, 1);
        rs1 += __shfl_xor_sync(0xffffffffu, rs1, 2);
        l0 = l0*a0 + rs0;  l1 = l1*a1 + rs1;
        m0 = mn0;          m1 = mn1;
#pragma unroll
        for (int j = 0; j < 8; j++) {
            ov[j][0] *= a0; ov[j][1] *= a0;
            ov[j][2] *= a1; ov[j][3] *= a1;
        }

        // ---- store P into Q buffer (fp16 pairs, same swizzle) ----
#pragma unroll
        for (int j = 0; j < 8; j++) {
            int pos = ((j ^ lr) << 2) | lc;     // ci=4j+lc swizzled
            sm_q[(r+lr  )*32 + pos] = pack_h2(sc[j][0], sc[j][1]);
            sm_q[(r+lr+8)*32 + pos] = pack_h2(sc[j][2], sc[j][3]);
        }
        CP_WAIT(1);             // V(kt) complete
        __syncthreads();        // (C) P + V visible

        // ---- PV: O[16q x 64d] += P @ V (B-frags via ldmatrix.trans) ----
#pragma unroll
        for (int ks = 0; ks < 4; ks++) {
            int cl  = ((2*ks    ) ^ lr)*4 + lc;
            int chh = ((2*ks + 1) ^ lr)*4 + lc;
            uint32_t pa[4];
            pa[0] = sm_q[(r+lr  )*32 + cl ];
            pa[1] = sm_q[(r+lr+8)*32 + cl ];
            pa[2] = sm_q[(r+lr  )*32 + chh];
            pa[3] = sm_q[(r+lr+8)*32 + chh];
            uint32_t vrow = sb_v + (uint32_t)((16*ks + krow)*32)*4u;
#pragma unroll
            for (int jp = 0; jp < 4; jp++) {
                int chv = (2*jp + clnof) ^ swz7;
                uint32_t v0, v1, v2, v3;
                ldsm4t(v0, v1, v2, v3, vrow + (uint32_t)(chv << 4));
                mma_f16(ov[2*jp    ], pa, v0, v1);
                mma_f16(ov[2*jp + 1], pa, v2, v3);
            }
        }
    }

    float inv0 = 1.0f / l0, inv1 = 1.0f / l1;
    int qq0 = q0 + r + lr, qq1 = qq0 + 8;
#pragma unroll
    for (int j = 0; j < 8; j++) {
        int d = 8*j + 2*lc;
        if (qq0 < S_) {
            float2 o2 = make_float2(ov[j][0]*inv0, ov[j][1]*inv0);
            *(float2*)&Op[(size_t)qq0*HD_ + d] = o2;
        }
        if (qq1 < S_) {
            float2 o2 = make_float2(ov[j][2]*inv1, ov[j][3]*inv1);
            *(float2*)&Op[(size_t)qq1*HD_ + d] = o2;
        }
    }
}

// ---------------------------------------------------------------------------
extern "C" void kernel_launch(void* const* d_in, const int* in_sizes, int n_in,
                              void* d_out, int out_size) {
    // metadata order: x1, h1, w1, x2, h2, w2, dw_w, bn_gamma, bn_beta, pw_w, pw_b, lin_w
    const float* x1  = (const float*)d_in[0];
    const float* x2  = (const float*)d_in[3];
    const float* dww = (const float*)d_in[6];
    const float* gam = (const float*)d_in[7];
    const float* bet = (const float*)d_in[8];
    const float* pw  = (const float*)d_in[9];
    const float* pwb = (const float*)d_in[10];
    const float* lin = (const float*)d_in[11];
    float* out = (float*)d_out;

    cudaFuncSetAttribute(gemm_kernel, cudaFuncAttributeMaxDynamicSharedMemorySize, 65536);
    cudaFuncSetAttribute(attn_kernel, cudaFuncAttributeMaxDynamicSharedMemorySize, 32768);

    dw_kernel   <<<dim3(16, 16, 3), 384>>>(x1, x2, dww);
    fold_kernel <<<dim3(6, 6, 9), 256>>>(pw, lin, gam, bet);
    bias_kernel <<<(NBI*C_*32 + 255)/256, 256>>>(lin, pwb);
    gemm_kernel <<<dim3(3, 98, 9), 256, 65536>>>();
    attn_kernel <<<dim3(13, 96, 3), 128, 32768>>>(out);
}

// round 16
// speedup vs baseline: 1.4681x; 1.0333x over previous
#include <cuda_runtime.h>
#include <cuda_fp16.h>
#include <math.h>
#include <stdint.h>

#define B_   16
#define C_   384
#define S_   784
#define NH_  6
#define HD_  64
#define NBI  9
#define NPART 256          // 16 batches * 16 spatial tiles
#define NTOK (B_*S_)       // 12544

// ---------------- scratch (static device globals; no allocation) ------------
__device__ unsigned short g_dw  [(size_t)NBI*NTOK*C_]; // fp16 bits of conv out [bi][tok][c]
__device__ unsigned short g_qkv [(size_t)NBI*NTOK*C_]; // fp16 [bi][b][h][s][d] (q pre-scaled by scale*log2e)
__device__ float          g_M   [NBI*C_*C_];           // combined lin@pw (fp32, for bias)
__device__ unsigned short g_Mt  [NBI*C_*C_];           // fp16 of M * a (gemm B operand)
__device__ float          g_psum[NBI*C_*NPART];
__device__ float          g_psq [NBI*C_*NPART];
__device__ float          g_a   [NBI*C_];
__device__ float          g_bc  [NBI*C_];
__device__ float          g_bias[NBI*C_];

// ---------------- helpers ---------------------------------------------------
__device__ __forceinline__ float ex2f(float x) {
    float r;
    asm("ex2.approx.f32 %0, %1;" : "=f"(r) : "f"(x));
    return r;
}

__device__ __forceinline__ uint32_t pack_h2(float lo, float hi) {
    uint32_t r;
    asm("cvt.rn.f16x2.f32 %0, %1, %2;" : "=r"(r) : "f"(hi), "f"(lo));  // 2nd src -> low half
    return r;
}

__device__ __forceinline__ void mma_f16(float c[4], const uint32_t a[4],
                                        uint32_t b0, uint32_t b1) {
    asm volatile(
        "mma.sync.aligned.m16n8k16.row.col.f32.f16.f16.f32 "
        "{%0,%1,%2,%3}, {%4,%5,%6,%7}, {%8,%9}, {%0,%1,%2,%3};\n"
        : "+f"(c[0]), "+f"(c[1]), "+f"(c[2]), "+f"(c[3])
        : "r"(a[0]), "r"(a[1]), "r"(a[2]), "r"(a[3]), "r"(b0), "r"(b1));
}

__device__ __forceinline__ void ldsm4(uint32_t& r0, uint32_t& r1, uint32_t& r2,
                                      uint32_t& r3, uint32_t addr) {
    asm volatile("ldmatrix.sync.aligned.m8n8.x4.shared.b16 {%0,%1,%2,%3}, [%4];"
        : "=r"(r0), "=r"(r1), "=r"(r2), "=r"(r3) : "r"(addr));
}

__device__ __forceinline__ void ldsm4t(uint32_t& r0, uint32_t& r1, uint32_t& r2,
                                       uint32_t& r3, uint32_t addr) {
    asm volatile("ldmatrix.sync.aligned.m8n8.x4.trans.shared.b16 {%0,%1,%2,%3}, [%4];"
        : "=r"(r0), "=r"(r1), "=r"(r2), "=r"(r3) : "r"(addr));
}

__device__ __forceinline__ uint32_t smem_u32(const void* p) {
    uint32_t a;
    asm("{ .reg .u64 t; cvta.to.shared.u64 t, %1; cvt.u32.u64 %0, t; }"
        : "=r"(a) : "l"(p));
    return a;
}

#define CP_A16(dst, src) \
    asm volatile("cp.async.ca.shared.global [%0], [%1], 16;\n" \
                 :: "r"(dst), "l"(src) : "memory")
#define CP_A16P(dst, src, ok) \
    asm volatile("cp.async.ca.shared.global [%0], [%1], 16, %2;\n" \
                 :: "r"(dst), "l"(src), "r"((ok) ? 16 : 0) : "memory")
#define CP_COMMIT() asm volatile("cp.async.commit_group;\n" ::: "memory")
#define CP_WAIT(n)  asm volatile("cp.async.wait_group %0;\n" :: "n"(n) : "memory")

// scale * log2e = 384^-0.5 * 1.4426950408889634
#define QSCALE 0.07362222f

// ---------------- 1) depthwise 3x3 conv (q,k,v fused) + BN partial stats ----
__global__ void dw_kernel(const float* __restrict__ x1, const float* __restrict__ x2,
                          const float* __restrict__ dww) {
    int c    = threadIdx.x;
    int tile = blockIdx.x;
    int b    = blockIdx.y;
    int br   = blockIdx.z;

    float w[3][9];
#pragma unroll
    for (int j = 0; j < 3; j++)
#pragma unroll
        for (int k = 0; k < 9; k++)
            w[j][k] = dww[((3*br+j)*C_ + c)*9 + k];

    const float* X1 = x1 + (size_t)b*S_*C_;
    const float* X2 = x2 + (size_t)b*S_*C_;
    unsigned short* out0 = g_dw + ((size_t)(3*br+0)*B_ + b)*(size_t)S_*C_;
    unsigned short* out1 = g_dw + ((size_t)(3*br+1)*B_ + b)*(size_t)S_*C_;
    unsigned short* out2 = g_dw + ((size_t)(3*br+2)*B_ + b)*(size_t)S_*C_;

    float sum[3] = {0.f,0.f,0.f}, sq[3] = {0.f,0.f,0.f};
    int s0 = tile*49;
    int y = s0 / 28, x = s0 - y*28;
    for (int i = 0; i < 49; i++) {
        int s = s0 + i;
        float a0 = 0.f, a1 = 0.f, a2 = 0.f;
#pragma unroll
        for (int ky = 0; ky < 3; ky++) {
            int yy = y + ky - 1;
            if (yy < 0 || yy >= 28) continue;
#pragma unroll
            for (int kx = 0; kx < 3; kx++) {
                int xx = x + kx - 1;
                if (xx < 0 || xx >= 28) continue;
                int sn = yy*28 + xx;
                float v;
                if      (br == 0) v = X1[sn*C_ + c];
                else if (br == 1) v = X2[sn*C_ + c];
                else              v = X1[sn*C_ + c] + X2[sn*C_ + c];
                int kk = ky*3 + kx;
                a0 += w[0][kk]*v;  a1 += w[1][kk]*v;  a2 += w[2][kk]*v;
            }
        }
        out0[s*C_ + c] = __half_as_ushort(__float2half_rn(a0));
        out1[s*C_ + c] = __half_as_ushort(__float2half_rn(a1));
        out2[s*C_ + c] = __half_as_ushort(__float2half_rn(a2));
        sum[0] += a0;  sq[0] += a0*a0;
        sum[1] += a1;  sq[1] += a1*a1;
        sum[2] += a2;  sq[2] += a2*a2;
        if (++x == 28) { x = 0; y++; }
    }
    int p = b*16 + tile;
#pragma unroll
    for (int j = 0; j < 3; j++) {
        int bi = 3*br + j;
        g_psum[(bi*C_ + c)*NPART + p] = sum[j];
        g_psq [(bi*C_ + c)*NPART + p] = sq[j];
    }
}

// ---------------- 2) fold: BN stats (absorbed) + M = lin@pw; Mt = fp16(M*a) -
__global__ void __launch_bounds__(256) fold_kernel(const float* __restrict__ pw,
                                                   const float* __restrict__ lin,
                                                   const float* __restrict__ gamma,
                                                   const float* __restrict__ beta) {
    __shared__ float s_a[64], s_bc[64];

    int bi = blockIdx.z;
    int br = bi / 3, j = bi - 3*br;
    int li = (br == 2 ? 3 : 3*br) + j;      // branch-3 reuses branch-2 lin weights
    const float* L = lin + (size_t)li*C_*C_;
    const float* P = pw  + (size_t)bi*C_*C_;

    int t  = threadIdx.x;
    int tx = t & 15, ty = t >> 4;
    int wid = t >> 5, lane = t & 31;
    int obase = blockIdx.y*64, cbase = blockIdx.x*64;

    // ---- BN stats for channels [cbase, cbase+64): warp per channel ----
    for (int cw = wid; cw < 64; cw += 8) {
        int gwc = bi*C_ + cbase + cw;
        const float* ps = g_psum + (size_t)gwc*NPART;
        const float* pq = g_psq  + (size_t)gwc*NPART;
        double s = 0.0, q = 0.0;
#pragma unroll
        for (int i = 0; i < NPART/32; i++) { s += ps[lane + i*32]; q += pq[lane + i*32]; }
#pragma unroll
        for (int o = 16; o > 0; o >>= 1) {
            s += __shfl_xor_sync(0xffffffffu, s, o);
            q += __shfl_xor_sync(0xffffffffu, q, o);
        }
        if (lane == 0) {
            const double N = (double)(B_*S_);
            float mu  = (float)(s / N);
            float var = (float)(q / N - (s/N)*(s/N));
            float a   = gamma[gwc] * rsqrtf(var + 1e-5f);
            float bc  = beta[gwc] - mu*a;
            s_a [cw] = a;   s_bc[cw] = bc;
            g_a [gwc] = a;  g_bc[gwc] = bc;
        }
    }

    __shared__ float As[16][65];
    __shared__ float Bs[16][65];
    float acc[4][4] = {};

    for (int k0 = 0; k0 < C_; k0 += 16) {
#pragma unroll
        for (int e = 0; e < 4; e++) {
            int idx = t + e*256;
            int kk = idx & 15, oo = idx >> 4;
            As[kk][oo] = L[(obase+oo)*C_ + k0 + kk];
        }
#pragma unroll
        for (int e = 0; e < 4; e++) {
            int cc = t & 63, kk = (t >> 6) + e*4;
            Bs[kk][cc] = P[(k0+kk)*C_ + cbase + cc];
        }
        __syncthreads();
#pragma unroll
        for (int kk = 0; kk < 16; kk++) {
            float ar[4], brr[4];
#pragma unroll
            for (int i = 0; i < 4; i++) ar[i]  = As[kk][ty*4+i];
#pragma unroll
            for (int jj = 0; jj < 4; jj++) brr[jj] = Bs[kk][tx*4+jj];
#pragma unroll
            for (int i = 0; i < 4; i++)
#pragma unroll
                for (int jj = 0; jj < 4; jj++) acc[i][jj] += ar[i]*brr[jj];
        }
        __syncthreads();
    }
    float*          Mo = g_M  + (size_t)bi*C_*C_;
    unsigned short* Mt = g_Mt + (size_t)bi*C_*C_;
#pragma unroll
    for (int i = 0; i < 4; i++)
#pragma unroll
        for (int jj = 0; jj < 4; jj++) {
            int oo = obase + ty*4 + i, ci = tx*4 + jj, cc = cbase + ci;
            Mo[oo*C_ + cc] = acc[i][jj];
            Mt[oo*C_ + cc] = __half_as_ushort(__float2half_rn(acc[i][jj] * s_a[ci]));
        }
}

// ---------------- 3) combined bias (warp per output) ------------------------
__global__ void bias_kernel(const float* __restrict__ lin, const float* __restrict__ pwb) {
    int gw   = (blockIdx.x*256 + threadIdx.x) >> 5;
    int lane = threadIdx.x & 31;
    if (gw >= NBI*C_) return;
    int bi = gw / C_, o = gw - bi*C_;
    int brr = bi/3, j = bi - 3*brr;
    int li = (brr == 2 ? 3 : 3*brr) + j;
    const float* L    = lin + ((size_t)li*C_ + o)*C_;
    const float* Pb   = pwb + (size_t)bi*C_;
    const float* Mrow = g_M + ((size_t)bi*C_ + o)*C_;
    const float* bc   = g_bc + (size_t)bi*C_;
    float s = 0.f;
    for (int k = lane; k < C_; k += 32) s += L[k]*Pb[k] + Mrow[k]*bc[k];
#pragma unroll
    for (int off = 16; off > 0; off >>= 1) s += __shfl_xor_sync(0xffffffffu, s, off);
    if (lane == 0) g_bias[gw] = s;
}

// ---------------- 4) main GEMM (fp16 m16n8k16, cp.async, ldmatrix frags) ----
// heads = dw @ (M*a)^T + bias; q tensors (bi%3==0) pre-scaled by scale*log2e.
// Block 128x128, BK=64 halves, 6 kt iters. Smem 65536 B. Fragment loads via
// ldmatrix.x4 (A non-trans, B non-trans on k-major n-rows): 24 LDSM/warp-kt
// replace 96 scalar LDS (ncu showed L1=64.3%).
__global__ void __launch_bounds__(256) gemm_kernel() {
    extern __shared__ uint32_t gsm[];
    uint32_t sb = smem_u32(gsm);
    // u32 offsets: As0 @0, As1 @4096, Bs0 @8192, Bs1 @12288

    int bi    = blockIdx.z;
    int rbase = blockIdx.y * 128;
    int obase = blockIdx.x * 128;
    const unsigned short* Ag = g_dw + (size_t)bi*NTOK*C_;
    const unsigned short* Bg = g_Mt + (size_t)bi*C_*C_;
    float qs = (bi % 3 == 0) ? QSCALE : 1.0f;

    int t    = threadIdx.x;
    int wid  = t >> 5, lane = t & 31;
    int wm   = wid >> 1, wn = wid & 1;
    int lr   = lane >> 2, lc = lane & 3;

    // ldmatrix lane addressing
    int a_row  = wm*32 + (lane & 7) + ((lane >> 3) & 1)*8;   // +16*i
    int a_cho  = lane >> 4;                                  // chunk offset 0/1
    int b_rowb = wn*64 + (lane & 7) + ((lane >> 4) << 3);    // +16*jp
    int b_cho  = (lane >> 3) & 1;

    float acc[2][8][4] = {};

    // prologue: stage 0 (each tile: 128 rows x 8 chunks of 16B)
    {
        uint32_t ab = sb, bb = sb + 8192u*4u;
#pragma unroll
        for (int e = 0; e < 4; e++) {
            int i = e*256 + t;
            int r = i >> 3, ch = i & 7;
            uint32_t dsto = (uint32_t)(r*32 + ((ch ^ (r&7)) << 2))*4u;
            CP_A16(ab + dsto, Ag + (size_t)(rbase+r)*C_ + ch*8);
            CP_A16(bb + dsto, Bg + (size_t)(obase+r)*C_ + ch*8);
        }
        CP_COMMIT();
    }

    for (int kt = 0; kt < 6; kt++) {
        __syncthreads();                         // prev MMA done; next stage free
        if (kt < 5) {
            int kbase = (kt+1)*64;               // in halves
            uint32_t st = (uint32_t)((kt+1) & 1);
            uint32_t ab = sb + st*4096u*4u;
            uint32_t bb = sb + (8192u + st*4096u)*4u;
#pragma unroll
            for (int e = 0; e < 4; e++) {
                int i = e*256 + t;
                int r = i >> 3, ch = i & 7;
                uint32_t dsto = (uint32_t)(r*32 + ((ch ^ (r&7)) << 2))*4u;
                CP_A16(ab + dsto, Ag + (size_t)(rbase+r)*C_ + kbase + ch*8);
                CP_A16(bb + dsto, Bg + (size_t)(obase+r)*C_ + kbase + ch*8);
            }
        }
        CP_COMMIT();
        CP_WAIT(1);
        __syncthreads();                         // stage kt ready & visible

        uint32_t As_b = sb + (uint32_t)(kt & 1)*4096u*4u;
        uint32_t Bs_b = sb + (uint32_t)(8192 + (kt & 1)*4096)*4u;
#pragma unroll
        for (int ks = 0; ks < 4; ks++) {
            uint32_t af[2][4];
#pragma unroll
            for (int i = 0; i < 2; i++) {
                int row = a_row + 16*i;
                int ch  = (2*ks + a_cho) ^ (row & 7);
                ldsm4(af[i][0], af[i][1], af[i][2], af[i][3],
                      As_b + (uint32_t)(row*32 + (ch << 2))*4u);
            }
#pragma unroll
            for (int jp = 0; jp < 4; jp++) {
                int row = b_rowb + 16*jp;
                int ch  = (2*ks + b_cho) ^ (row & 7);
                uint32_t bf0, bf1, bf2, bf3;
                ldsm4(bf0, bf1, bf2, bf3,
                      Bs_b + (uint32_t)(row*32 + (ch << 2))*4u);
#pragma unroll
                for (int i = 0; i < 2; i++) {
                    mma_f16(acc[i][2*jp    ], af[i], bf0, bf1);
                    mma_f16(acc[i][2*jp + 1], af[i], bf2, bf3);
                }
            }
        }
    }

    // epilogue: fp16 bits of (acc + bias)*qs into [bi][b][h][s][d]
    const float* bias = g_bias + (size_t)bi*C_;
#pragma unroll
    for (int i = 0; i < 2; i++) {
        int r0 = rbase + wm*32 + i*16 + lr;
        int r1 = r0 + 8;
        int b0r = r0 / S_, s0r = r0 - b0r*S_;
        int b1r = r1 / S_, s1r = r1 - b1r*S_;
#pragma unroll
        for (int j = 0; j < 8; j++) {
            int o = obase + wn*64 + j*8 + 2*lc;   // even
            int h = o >> 6, d = o & 63;
            float bo0 = bias[o], bo1 = bias[o+1];
            uint32_t* d0 = (uint32_t*)(g_qkv + ((((size_t)bi*B_ + b0r)*NH_ + h)*S_ + s0r)*HD_ + d);
            *d0 = pack_h2((acc[i][j][0] + bo0) * qs, (acc[i][j][1] + bo1) * qs);
            uint32_t* d1 = (uint32_t*)(g_qkv + ((((size_t)bi*B_ + b1r)*NH_ + h)*S_ + s1r)*HD_ + d);
            *d1 = pack_h2((acc[i][j][2] + bo0) * qs, (acc[i][j][3] + bo1) * qs);
        }
    }
}

// ---------------- 5) flash attention (register-P, 2-stage K+V) --------------
// 128 thr / 4 warps, TQ=64, TK=64. Smem 40 KB: Q 8K, K 2x8K, V 2x8K -> 4
// blocks/SM. P stays in registers: QK accumulator layout == PV A-fragment
// layout (pa = pack_h2 of sc pairs). 2 syncthreads/iter; one cp.async group
// (K+V) per tile, wait(1) ledger.
__global__ void __launch_bounds__(128, 4) attn_kernel(float* __restrict__ out) {
    extern __shared__ uint32_t smem[];
    uint32_t* sm_q = smem;               // 64*32 u32 (Q only)
    uint32_t* sm_k = smem + 2048;        // 2 x 64*32
    uint32_t sb   = smem_u32(smem);
    uint32_t sb_k = sb + 2048u*4u;
    uint32_t sb_v = sb + 6144u*4u;       // 2 x 64*32

    int t    = threadIdx.x;
    int wid  = t >> 5, lane = t & 31;
    int lr   = lane >> 2, lc = lane & 3;
    int qt   = blockIdx.x;               // 13 q-tiles of 64
    int bh   = blockIdx.y;
    int br   = blockIdx.z;
    int b = bh / NH_, h = bh - b*NH_;

    const unsigned short* Qg = g_qkv + (((size_t)(3*br+0)*B_ + b)*NH_ + h)*(size_t)S_*HD_;
    const unsigned short* Kg = g_qkv + (((size_t)(3*br+1)*B_ + b)*NH_ + h)*(size_t)S_*HD_;
    const unsigned short* Vg = g_qkv + (((size_t)(3*br+2)*B_ + b)*NH_ + h)*(size_t)S_*HD_;
    float* Op = out + ((size_t)br*B_ + b)*(size_t)S_*C_ + (size_t)h*S_*HD_;

    int q0 = qt*64;

    // prologue: async Q; then KV(0) as one group into stage 0
#pragma unroll
    for (int e = 0; e < 4; e++) {
        int i = e*128 + t;
        int q = i >> 3, ch = i & 7;
        int qg = q0 + q;
        const unsigned short* src = Qg + (size_t)(qg < S_ ? qg : S_-1)*HD_ + ch*8;
        CP_A16P(sb + (uint32_t)(q*32 + ((ch ^ (q&7)) << 2))*4u, src, qg < S_);
    }
    CP_COMMIT();
#pragma unroll
    for (int e = 0; e < 4; e++) {
        int i = e*128 + t;
        int k = i >> 3, ch = i & 7;
        uint32_t dsto = (uint32_t)(k*32 + ((ch ^ (k&7)) << 2))*4u;
        CP_A16(sb_k + dsto, Kg + (size_t)k*HD_ + ch*8);
        CP_A16(sb_v + dsto, Vg + (size_t)k*HD_ + ch*8);
    }
    CP_COMMIT();
    CP_WAIT(1);            // Q ready (KV0 may be in flight)
    __syncthreads();

    // hoist Q A-frags (warp w owns rows 16w..16w+15)
    int r = wid * 16;
    uint32_t qa[4][4];
#pragma unroll
    for (int ks = 0; ks < 4; ks++) {
        int cl  = ((2*ks    ) ^ lr)*4 + lc;
        int chh = ((2*ks + 1) ^ lr)*4 + lc;
        qa[ks][0] = sm_q[(r+lr  )*32 + cl ];
        qa[ks][1] = sm_q[(r+lr+8)*32 + cl ];
        qa[ks][2] = sm_q[(r+lr  )*32 + chh];
        qa[ks][3] = sm_q[(r+lr+8)*32 + chh];
    }

    // lane constants for ldmatrix V addressing
    int krow  = ((lane >> 3) & 1)*8 + (lane & 7);   // row within 16-k chunk
    int clnof = lane >> 4;                          // 0/1: chunk pair selector
    int swz7  = lane & 7;                           // = krow&7

    float ov[8][4] = {};
    float m0 = -1e30f, m1 = -1e30f, l0 = 0.f, l1 = 0.f;

    for (int kt = 0; kt < 13; kt++) {
        __syncthreads();        // (A) all warps done with compute(kt-1) -> stage (kt+1)&1 free

        // issue KV(kt+1) as one group
        if (kt < 12) {
            int kn = (kt+1)*64;
            uint32_t st = (uint32_t)((kt+1) & 1)*8192u;
#pragma unroll
            for (int e = 0; e < 4; e++) {
                int i = e*128 + t;
                int k = i >> 3, ch = i & 7;
                int kg = kn + k;
                uint32_t dsto = (uint32_t)(k*32 + ((ch ^ (k&7)) << 2))*4u;
                const unsigned short* srcK = Kg + (size_t)(kg < S_ ? kg : S_-1)*HD_ + ch*8;
                const unsigned short* srcV = Vg + (size_t)(kg < S_ ? kg : S_-1)*HD_ + ch*8;
                CP_A16P(sb_k + st + dsto, srcK, kg < S_);
                CP_A16P(sb_v + st + dsto, srcV, kg < S_);
            }
        }
        CP_COMMIT();
        CP_WAIT(1);             // KV(kt) complete
        __syncthreads();        // (B) KV(kt) visible

        const uint32_t* Ks_ = sm_k + (kt & 1)*2048;
        uint32_t vb = sb_v + (uint32_t)(kt & 1)*8192u;

        // ---- scores: S[16q x 64k] per warp (log2 units) ----
        float sc[8][4] = {};
#pragma unroll
        for (int ks = 0; ks < 4; ks++) {
            int cl  = ((2*ks    ) ^ lr)*4 + lc;
            int chh = ((2*ks + 1) ^ lr)*4 + lc;
#pragma unroll
            for (int j = 0; j < 8; j++) {
                uint32_t b0 = Ks_[(8*j+lr)*32 + cl ];
                uint32_t b1 = Ks_[(8*j+lr)*32 + chh];
                mma_f16(sc[j], qa[ks], b0, b1);
            }
        }

        // ---- masking: only last k-tile ----
        if (kt == 12) {
#pragma unroll
            for (int j = 0; j < 8; j++) {
                int col = 768 + 8*j + 2*lc;
                if (col     >= S_) { sc[j][0] = -1e30f; sc[j][2] = -1e30f; }
                if (col + 1 >= S_) { sc[j][1] = -1e30f; sc[j][3] = -1e30f; }
            }
        }

        // ---- online softmax, log2 domain ----
        float mx0 = -1e30f, mx1 = -1e30f;
#pragma unroll
        for (int j = 0; j < 8; j++) {
            mx0 = fmaxf(mx0, fmaxf(sc[j][0], sc[j][1]));
            mx1 = fmaxf(mx1, fmaxf(sc[j][2], sc[j][3]));
        }
        mx0 = fmaxf(mx0, __shfl_xor_sync(0xffffffffu, mx0, 1));
        mx0 = fmaxf(mx0, __shfl_xor_sync(0xffffffffu, mx0, 2));
        mx1 = fmaxf(mx1, __shfl_xor_sync(0xffffffffu, mx1, 1));
        mx1 = fmaxf(mx1, __shfl_xor_sync(0xffffffffu, mx1, 2));
        float mn0 = fmaxf(m0, mx0), mn1 = fmaxf(m1, mx1);
        float a0  = ex2f(m0 - mn0), a1 = ex2f(m1 - mn1);
        float rs0 = 0.f, rs1 = 0.f;
#pragma unroll
        for (int j = 0; j < 8; j++) {
            sc[j][0] = ex2f(sc[j][0] - mn0); rs0 += sc[j][0];
            sc[j][1] = ex2f(sc[j][1] - mn0); rs0 += sc[j][1];
            sc[j][2] = ex2f(sc[j][2] - mn1); rs1 += sc[j][2];
            sc[j][3] = ex2f(sc[j][3] - mn1); rs1 += sc[j][3];
        }
        rs0 += __shfl_xor_sync(0xffffffffu, rs0, 1);
        rs0 += __shfl_xor_sync(0xffffffffu, rs0, 2);
        rs1 += __shfl_xor_sync(0xffffffffu, rs1, 1);
        rs1 += __shfl_xor_sync(0xffffffffu, rs1, 2);
        l0 = l0*a0 + rs0;  l1 = l1*a1 + rs1;
        m0 = mn0;          m1 = mn1;
#pragma unroll
        for (int j = 0; j < 8; j++) {
            ov[j][0] *= a0; ov[j][1] *= a0;
            ov[j][2] *= a1; ov[j][3] *= a1;
        }

        // ---- PV: O += P @ V, P direct from registers (QK acc == PV A-frag) --
#pragma unroll
        for (int ks = 0; ks < 4; ks++) {
            uint32_t pa[4];
            pa[0] = pack_h2(sc[2*ks  ][0], sc[2*ks  ][1]);
            pa[1] = pack_h2(sc[2*ks  ][2], sc[2*ks  ][3]);
            pa[2] = pack_h2(sc[2*ks+1][0], sc[2*ks+1][1]);
            pa[3] = pack_h2(sc[2*ks+1][2], sc[2*ks+1][3]);
            uint32_t vrow = vb + (uint32_t)((16*ks + krow)*32)*4u;
#pragma unroll
            for (int jp = 0; jp < 4; jp++) {
                int chv = (2*jp + clnof) ^ swz7;
                uint32_t v0, v1, v2, v3;
                ldsm4t(v0, v1, v2, v3, vrow + (uint32_t)(chv << 4));
                mma_f16(ov[2*jp    ], pa, v0, v1);
                mma_f16(ov[2*jp + 1], pa, v2, v3);
            }
        }
    }

    float inv0 = 1.0f / l0, inv1 = 1.0f / l1;
    int qq0 = q0 + r + lr, qq1 = qq0 + 8;
#pragma unroll
    for (int j = 0; j < 8; j++) {
        int d = 8*j + 2*lc;
        if (qq0 < S_) {
            float2 o2 = make_float2(ov[j][0]*inv0, ov[j][1]*inv0);
            *(float2*)&Op[(size_t)qq0*HD_ + d] = o2;
        }
        if (qq1 < S_) {
            float2 o2 = make_float2(ov[j][2]*inv1, ov[j][3]*inv1);
            *(float2*)&Op[(size_t)qq1*HD_ + d] = o2;
        }
    }
}

// ---------------------------------------------------------------------------
extern "C" void kernel_launch(void* const* d_in, const int* in_sizes, int n_in,
                              void* d_out, int out_size) {
    // metadata order: x1, h1, w1, x2, h2, w2, dw_w, bn_gamma, bn_beta, pw_w, pw_b, lin_w
    const float* x1  = (const float*)d_in[0];
    const float* x2  = (const float*)d_in[3];
    const float* dww = (const float*)d_in[6];
    const float* gam = (const float*)d_in[7];
    const float* bet = (const float*)d_in[8];
    const float* pw  = (const float*)d_in[9];
    const float* pwb = (const float*)d_in[10];
    const float* lin = (const float*)d_in[11];
    float* out = (float*)d_out;

    cudaFuncSetAttribute(gemm_kernel, cudaFuncAttributeMaxDynamicSharedMemorySize, 65536);
    cudaFuncSetAttribute(attn_kernel, cudaFuncAttributeMaxDynamicSharedMemorySize, 40960);

    dw_kernel   <<<dim3(16, 16, 3), 384>>>(x1, x2, dww);
    fold_kernel <<<dim3(6, 6, 9), 256>>>(pw, lin, gam, bet);
    bias_kernel <<<(NBI*C_*32 + 255)/256, 256>>>(lin, pwb);
    gemm_kernel <<<dim3(3, 98, 9), 256, 65536>>>();
    attn_kernel <<<dim3(13, 96, 3), 128, 40960>>>(out);
}

// round 17
// speedup vs baseline: 1.9836x; 1.3511x over previous
#include <cuda_runtime.h>
#include <cuda_fp16.h>
#include <math.h>
#include <stdint.h>

#define B_   16
#define C_   384
#define S_   784
#define NH_  6
#define HD_  64
#define NBI  9
#define NPART 224          // 16 batches * 14 two-row tiles
#define NTOK (B_*S_)       // 12544

// ---------------- scratch (static device globals; no allocation) ------------
__device__ unsigned short g_dw  [(size_t)NBI*NTOK*C_]; // fp16 bits of conv out [bi][tok][c]
__device__ unsigned short g_qkv [(size_t)NBI*NTOK*C_]; // fp16 [bi][b][h][s][d] (q pre-scaled by scale*log2e)
__device__ unsigned short g_Mt  [NBI*C_*C_];           // fp16 of M * a (gemm B operand)
__device__ float          g_psum[NBI*C_*NPART];
__device__ float          g_psq [NBI*C_*NPART];
__device__ float          g_biasp[NBI*6*C_];           // partial biases per 64-col chunk

// ---------------- helpers ---------------------------------------------------
__device__ __forceinline__ float ex2f(float x) {
    float r;
    asm("ex2.approx.f32 %0, %1;" : "=f"(r) : "f"(x));
    return r;
}

__device__ __forceinline__ uint32_t pack_h2(float lo, float hi) {
    uint32_t r;
    asm("cvt.rn.f16x2.f32 %0, %1, %2;" : "=r"(r) : "f"(hi), "f"(lo));  // 2nd src -> low half
    return r;
}

__device__ __forceinline__ void mma_f16(float c[4], const uint32_t a[4],
                                        uint32_t b0, uint32_t b1) {
    asm volatile(
        "mma.sync.aligned.m16n8k16.row.col.f32.f16.f16.f32 "
        "{%0,%1,%2,%3}, {%4,%5,%6,%7}, {%8,%9}, {%0,%1,%2,%3};\n"
        : "+f"(c[0]), "+f"(c[1]), "+f"(c[2]), "+f"(c[3])
        : "r"(a[0]), "r"(a[1]), "r"(a[2]), "r"(a[3]), "r"(b0), "r"(b1));
}

__device__ __forceinline__ void ldsm4(uint32_t& r0, uint32_t& r1, uint32_t& r2,
                                      uint32_t& r3, uint32_t addr) {
    asm volatile("ldmatrix.sync.aligned.m8n8.x4.shared.b16 {%0,%1,%2,%3}, [%4];"
        : "=r"(r0), "=r"(r1), "=r"(r2), "=r"(r3) : "r"(addr));
}

__device__ __forceinline__ void ldsm4t(uint32_t& r0, uint32_t& r1, uint32_t& r2,
                                       uint32_t& r3, uint32_t addr) {
    asm volatile("ldmatrix.sync.aligned.m8n8.x4.trans.shared.b16 {%0,%1,%2,%3}, [%4];"
        : "=r"(r0), "=r"(r1), "=r"(r2), "=r"(r3) : "r"(addr));
}

__device__ __forceinline__ uint32_t smem_u32(const void* p) {
    uint32_t a;
    asm("{ .reg .u64 t; cvta.to.shared.u64 t, %1; cvt.u32.u64 %0, t; }"
        : "=r"(a) : "l"(p));
    return a;
}

#define CP_A16(dst, src) \
    asm volatile("cp.async.ca.shared.global [%0], [%1], 16;\n" \
                 :: "r"(dst), "l"(src) : "memory")
#define CP_A16P(dst, src, ok) \
    asm volatile("cp.async.ca.shared.global [%0], [%1], 16, %2;\n" \
                 :: "r"(dst), "l"(src), "r"((ok) ? 16 : 0) : "memory")
#define CP_COMMIT() asm volatile("cp.async.commit_group;\n" ::: "memory")
#define CP_WAIT(n)  asm volatile("cp.async.wait_group %0;\n" :: "n"(n) : "memory")

// scale * log2e = 384^-0.5 * 1.4426950408889634
#define QSCALE 0.07362222f

// ---------------- 1) depthwise 3x3 conv, rolling-window (2 rows / block) ----
// Tile = 2 output rows x 28 cols; register window of 3 cols x 4 input rows ->
// 4 LDG per column step (~116/thread vs 441 before). q,k,v fused per branch.
__global__ void dw_kernel(const float* __restrict__ x1, const float* __restrict__ x2,
                          const float* __restrict__ dww) {
    int c    = threadIdx.x;        // 0..383
    int tile = blockIdx.x;         // 14 tiles of 2 rows
    int b    = blockIdx.y;
    int br   = blockIdx.z;
    int y0   = tile*2;

    float w[3][9];
#pragma unroll
    for (int j = 0; j < 3; j++)
#pragma unroll
        for (int k = 0; k < 9; k++)
            w[j][k] = dww[((3*br+j)*C_ + c)*9 + k];

    const float* X1 = x1 + (size_t)b*S_*C_;
    const float* X2 = x2 + (size_t)b*S_*C_;
    unsigned short* out0 = g_dw + ((size_t)(3*br+0)*B_ + b)*(size_t)S_*C_;
    unsigned short* out1 = g_dw + ((size_t)(3*br+1)*B_ + b)*(size_t)S_*C_;
    unsigned short* out2 = g_dw + ((size_t)(3*br+2)*B_ + b)*(size_t)S_*C_;

    float sum[3] = {0.f,0.f,0.f}, sq[3] = {0.f,0.f,0.f};

    float cb0[4], cb1[4], cb2[4];
    auto ldcol = [&](float* dst, int xx) {
#pragma unroll
        for (int ry = 0; ry < 4; ry++) {
            int yy = y0 - 1 + ry;
            float v = 0.f;
            if (xx >= 0 && xx < 28 && yy >= 0 && yy < 28) {
                int sn = yy*28 + xx;
                if      (br == 0) v = X1[sn*C_ + c];
                else if (br == 1) v = X2[sn*C_ + c];
                else              v = X1[sn*C_ + c] + X2[sn*C_ + c];
            }
            dst[ry] = v;
        }
    };
    ldcol(cb0, -1);
    ldcol(cb1, 0);
    ldcol(cb2, 1);

    for (int x = 0; x < 28; x++) {
        int s_lo = y0*28 + x, s_hi = s_lo + 28;
#pragma unroll
        for (int j = 0; j < 3; j++) {
            float a0 = 0.f, a1 = 0.f;
#pragma unroll
            for (int ry = 0; ry < 3; ry++) {
                a0 += w[j][ry*3+0]*cb0[ry]   + w[j][ry*3+1]*cb1[ry]   + w[j][ry*3+2]*cb2[ry];
                a1 += w[j][ry*3+0]*cb0[ry+1] + w[j][ry*3+1]*cb1[ry+1] + w[j][ry*3+2]*cb2[ry+1];
            }
            unsigned short h0 = __half_as_ushort(__float2half_rn(a0));
            unsigned short h1 = __half_as_ushort(__float2half_rn(a1));
            if      (j == 0) { out0[s_lo*C_ + c] = h0; out0[s_hi*C_ + c] = h1; }
            else if (j == 1) { out1[s_lo*C_ + c] = h0; out1[s_hi*C_ + c] = h1; }
            else             { out2[s_lo*C_ + c] = h0; out2[s_hi*C_ + c] = h1; }
            sum[j] += a0 + a1;
            sq[j]  += a0*a0 + a1*a1;
        }
        // shift window, load col x+2
#pragma unroll
        for (int ry = 0; ry < 4; ry++) { cb0[ry] = cb1[ry]; cb1[ry] = cb2[ry]; }
        ldcol(cb2, x + 2);
    }

    int p = b*14 + tile;
#pragma unroll
    for (int j = 0; j < 3; j++) {
        int bi = 3*br + j;
        g_psum[(bi*C_ + c)*NPART + p] = sum[j];
        g_psq [(bi*C_ + c)*NPART + p] = sq[j];
    }
}

// ---------------- 2) fold: BN stats + M = lin@pw; Mt = fp16(M*a); partial bias
// Each block also emits its partial bias: pb[o] = sum_{c in tile} M[o,c]*bc[c]
// (+ tx-strided L@pwb for blockIdx.x==0), shuffle-reduced over tx. Fixed-order
// sums -> deterministic. gemm_kernel sums the 6 partials.
__global__ void __launch_bounds__(256) fold_kernel(const float* __restrict__ pw,
                                                   const float* __restrict__ lin,
                                                   const float* __restrict__ gamma,
                                                   const float* __restrict__ beta,
                                                   const float* __restrict__ pwb) {
    __shared__ float s_a[64], s_bc[64];
    __shared__ float s_pbv[C_];

    int bi = blockIdx.z;
    int br = bi / 3, j = bi - 3*br;
    int li = (br == 2 ? 3 : 3*br) + j;      // branch-3 reuses branch-2 lin weights
    const float* L = lin + (size_t)li*C_*C_;
    const float* P = pw  + (size_t)bi*C_*C_;
    const float* Pb = pwb + (size_t)bi*C_;

    int t  = threadIdx.x;
    int tx = t & 15, ty = t >> 4;
    int wid = t >> 5, lane = t & 31;
    int obase = blockIdx.y*64, cbase = blockIdx.x*64;

    // pwb into smem
    for (int idx = t; idx < C_; idx += 256) s_pbv[idx] = Pb[idx];

    // ---- BN stats for channels [cbase, cbase+64): warp per channel ----
    for (int cw = wid; cw < 64; cw += 8) {
        int gwc = bi*C_ + cbase + cw;
        const float* ps = g_psum + (size_t)gwc*NPART;
        const float* pq = g_psq  + (size_t)gwc*NPART;
        double s = 0.0, q = 0.0;
#pragma unroll
        for (int i = 0; i < NPART/32; i++) { s += ps[lane + i*32]; q += pq[lane + i*32]; }
#pragma unroll
        for (int o = 16; o > 0; o >>= 1) {
            s += __shfl_xor_sync(0xffffffffu, s, o);
            q += __shfl_xor_sync(0xffffffffu, q, o);
        }
        if (lane == 0) {
            const double N = (double)(B_*S_);
            float mu  = (float)(s / N);
            float var = (float)(q / N - (s/N)*(s/N));
            float a   = gamma[gwc] * rsqrtf(var + 1e-5f);
            s_a [cw] = a;
            s_bc[cw] = beta[gwc] - mu*a;
        }
    }

    __shared__ float As[16][65];
    __shared__ float Bs[16][65];
    float acc[4][4] = {};

    for (int k0 = 0; k0 < C_; k0 += 16) {
#pragma unroll
        for (int e = 0; e < 4; e++) {
            int idx = t + e*256;
            int kk = idx & 15, oo = idx >> 4;
            As[kk][oo] = L[(obase+oo)*C_ + k0 + kk];
        }
#pragma unroll
        for (int e = 0; e < 4; e++) {
            int cc = t & 63, kk = (t >> 6) + e*4;
            Bs[kk][cc] = P[(k0+kk)*C_ + cbase + cc];
        }
        __syncthreads();
#pragma unroll
        for (int kk = 0; kk < 16; kk++) {
            float ar[4], brr[4];
#pragma unroll
            for (int i = 0; i < 4; i++) ar[i]  = As[kk][ty*4+i];
#pragma unroll
            for (int jj = 0; jj < 4; jj++) brr[jj] = Bs[kk][tx*4+jj];
#pragma unroll
            for (int i = 0; i < 4; i++)
#pragma unroll
                for (int jj = 0; jj < 4; jj++) acc[i][jj] += ar[i]*brr[jj];
        }
        __syncthreads();
    }

    unsigned short* Mt = g_Mt + (size_t)bi*C_*C_;
#pragma unroll
    for (int i = 0; i < 4; i++)
#pragma unroll
        for (int jj = 0; jj < 4; jj++) {
            int oo = obase + ty*4 + i, ci = tx*4 + jj, cc = cbase + ci;
            Mt[oo*C_ + cc] = __half_as_ushort(__float2half_rn(acc[i][jj] * s_a[ci]));
        }

    // ---- partial bias ----
    float pbt[4];
#pragma unroll
    for (int i = 0; i < 4; i++) {
        float s = 0.f;
#pragma unroll
        for (int jj = 0; jj < 4; jj++) s += acc[i][jj] * s_bc[tx*4+jj];
        pbt[i] = s;
    }
    if (blockIdx.x == 0) {
        // tx-strided L@pwb term (reduced together with pbt below)
#pragma unroll
        for (int i = 0; i < 4; i++) {
            const float* Lr = L + (size_t)(obase + ty*4 + i)*C_;
            float s = 0.f;
            for (int k = tx; k < C_; k += 16) s += Lr[k] * s_pbv[k];
            pbt[i] += s;
        }
    }
#pragma unroll
    for (int o = 8; o >= 1; o >>= 1)
#pragma unroll
        for (int i = 0; i < 4; i++)
            pbt[i] += __shfl_xor_sync(0xffffffffu, pbt[i], o);
    if (tx == 0) {
#pragma unroll
        for (int i = 0; i < 4; i++)
            g_biasp[((size_t)bi*6 + blockIdx.x)*C_ + obase + ty*4 + i] = pbt[i];
    }
}

// ---------------- 3) main GEMM (fp16 m16n8k16, cp.async, ldmatrix frags) ----
// heads = dw @ (M*a)^T + bias; q tensors (bi%3==0) pre-scaled by scale*log2e.
// Bias assembled in prologue from the 6 fold partials (fixed order).
__global__ void __launch_bounds__(256) gemm_kernel() {
    extern __shared__ uint32_t gsm[];
    uint32_t sb = smem_u32(gsm);
    // u32 offsets: As0 @0, As1 @4096, Bs0 @8192, Bs1 @12288, bias @16384 (128 f32)
    float* sm_bias = (float*)(gsm + 16384);

    int bi    = blockIdx.z;
    int rbase = blockIdx.y * 128;
    int obase = blockIdx.x * 128;
    const unsigned short* Ag = g_dw + (size_t)bi*NTOK*C_;
    const unsigned short* Bg = g_Mt + (size_t)bi*C_*C_;
    float qs = (bi % 3 == 0) ? QSCALE : 1.0f;

    int t    = threadIdx.x;
    int wid  = t >> 5, lane = t & 31;
    int wm   = wid >> 1, wn = wid & 1;
    int lr   = lane >> 2, lc = lane & 3;

    // ldmatrix lane addressing
    int a_row  = wm*32 + (lane & 7) + ((lane >> 3) & 1)*8;   // +16*i
    int a_cho  = lane >> 4;                                  // chunk offset 0/1
    int b_rowb = wn*64 + (lane & 7) + ((lane >> 4) << 3);    // +16*jp
    int b_cho  = (lane >> 3) & 1;

    float acc[2][8][4] = {};

    // bias gather (6 partials, fixed order)
    if (t < 128) {
        float s = 0.f;
#pragma unroll
        for (int cx = 0; cx < 6; cx++)
            s += g_biasp[((size_t)bi*6 + cx)*C_ + obase + t];
        sm_bias[t] = s;
    }

    // prologue: stage 0 (each tile: 128 rows x 8 chunks of 16B)
    {
        uint32_t ab = sb, bb = sb + 8192u*4u;
#pragma unroll
        for (int e = 0; e < 4; e++) {
            int i = e*256 + t;
            int r = i >> 3, ch = i & 7;
            uint32_t dsto = (uint32_t)(r*32 + ((ch ^ (r&7)) << 2))*4u;
            CP_A16(ab + dsto, Ag + (size_t)(rbase+r)*C_ + ch*8);
            CP_A16(bb + dsto, Bg + (size_t)(obase+r)*C_ + ch*8);
        }
        CP_COMMIT();
    }

    for (int kt = 0; kt < 6; kt++) {
        __syncthreads();                         // prev MMA done; next stage free
        if (kt < 5) {
            int kbase = (kt+1)*64;               // in halves
            uint32_t st = (uint32_t)((kt+1) & 1);
            uint32_t ab = sb + st*4096u*4u;
            uint32_t bb = sb + (8192u + st*4096u)*4u;
#pragma unroll
            for (int e = 0; e < 4; e++) {
                int i = e*256 + t;
                int r = i >> 3, ch = i & 7;
                uint32_t dsto = (uint32_t)(r*32 + ((ch ^ (r&7)) << 2))*4u;
                CP_A16(ab + dsto, Ag + (size_t)(rbase+r)*C_ + kbase + ch*8);
                CP_A16(bb + dsto, Bg + (size_t)(obase+r)*C_ + kbase + ch*8);
            }
        }
        CP_COMMIT();
        CP_WAIT(1);
        __syncthreads();                         // stage kt ready & visible

        uint32_t As_b = sb + (uint32_t)(kt & 1)*4096u*4u;
        uint32_t Bs_b = sb + (uint32_t)(8192 + (kt & 1)*4096)*4u;
#pragma unroll
        for (int ks = 0; ks < 4; ks++) {
            uint32_t af[2][4];
#pragma unroll
            for (int i = 0; i < 2; i++) {
                int row = a_row + 16*i;
                int ch  = (2*ks + a_cho) ^ (row & 7);
                ldsm4(af[i][0], af[i][1], af[i][2], af[i][3],
                      As_b + (uint32_t)(row*32 + (ch << 2))*4u);
            }
#pragma unroll
            for (int jp = 0; jp < 4; jp++) {
                int row = b_rowb + 16*jp;
                int ch  = (2*ks + b_cho) ^ (row & 7);
                uint32_t bf0, bf1, bf2, bf3;
                ldsm4(bf0, bf1, bf2, bf3,
                      Bs_b + (uint32_t)(row*32 + (ch << 2))*4u);
#pragma unroll
                for (int i = 0; i < 2; i++) {
                    mma_f16(acc[i][2*jp    ], af[i], bf0, bf1);
                    mma_f16(acc[i][2*jp + 1], af[i], bf2, bf3);
                }
            }
        }
    }

    // epilogue: fp16 bits of (acc + bias)*qs into [bi][b][h][s][d]
#pragma unroll
    for (int i = 0; i < 2; i++) {
        int r0 = rbase + wm*32 + i*16 + lr;
        int r1 = r0 + 8;
        int b0r = r0 / S_, s0r = r0 - b0r*S_;
        int b1r = r1 / S_, s1r = r1 - b1r*S_;
#pragma unroll
        for (int j = 0; j < 8; j++) {
            int ol = wn*64 + j*8 + 2*lc;          // local o (even)
            int o  = obase + ol;
            int h = o >> 6, d = o & 63;
            float bo0 = sm_bias[ol], bo1 = sm_bias[ol+1];
            uint32_t* d0 = (uint32_t*)(g_qkv + ((((size_t)bi*B_ + b0r)*NH_ + h)*S_ + s0r)*HD_ + d);
            *d0 = pack_h2((acc[i][j][0] + bo0) * qs, (acc[i][j][1] + bo1) * qs);
            uint32_t* d1 = (uint32_t*)(g_qkv + ((((size_t)bi*B_ + b1r)*NH_ + h)*S_ + s1r)*HD_ + d);
            *d1 = pack_h2((acc[i][j][2] + bo0) * qs, (acc[i][j][3] + bo1) * qs);
        }
    }
}

// ---------------- 4) flash attention (register-P, 2-stage K+V) --------------
// 128 thr / 4 warps, TQ=64, TK=64. Smem 40 KB -> 4 blocks/SM. P stays in
// registers (QK acc layout == PV A-frag layout). 2 syncthreads/iter.
__global__ void __launch_bounds__(128, 4) attn_kernel(float* __restrict__ out) {
    extern __shared__ uint32_t smem[];
    uint32_t* sm_q = smem;               // 64*32 u32 (Q only)
    uint32_t* sm_k = smem + 2048;        // 2 x 64*32
    uint32_t sb   = smem_u32(smem);
    uint32_t sb_k = sb + 2048u*4u;
    uint32_t sb_v = sb + 6144u*4u;       // 2 x 64*32

    int t    = threadIdx.x;
    int wid  = t >> 5, lane = t & 31;
    int lr   = lane >> 2, lc = lane & 3;
    int qt   = blockIdx.x;               // 13 q-tiles of 64
    int bh   = blockIdx.y;
    int br   = blockIdx.z;
    int b = bh / NH_, h = bh - b*NH_;

    const unsigned short* Qg = g_qkv + (((size_t)(3*br+0)*B_ + b)*NH_ + h)*(size_t)S_*HD_;
    const unsigned short* Kg = g_qkv + (((size_t)(3*br+1)*B_ + b)*NH_ + h)*(size_t)S_*HD_;
    const unsigned short* Vg = g_qkv + (((size_t)(3*br+2)*B_ + b)*NH_ + h)*(size_t)S_*HD_;
    float* Op = out + ((size_t)br*B_ + b)*(size_t)S_*C_ + (size_t)h*S_*HD_;

    int q0 = qt*64;

    // prologue: async Q; then KV(0) as one group into stage 0
#pragma unroll
    for (int e = 0; e < 4; e++) {
        int i = e*128 + t;
        int q = i >> 3, ch = i & 7;
        int qg = q0 + q;
        const unsigned short* src = Qg + (size_t)(qg < S_ ? qg : S_-1)*HD_ + ch*8;
        CP_A16P(sb + (uint32_t)(q*32 + ((ch ^ (q&7)) << 2))*4u, src, qg < S_);
    }
    CP_COMMIT();
#pragma unroll
    for (int e = 0; e < 4; e++) {
        int i = e*128 + t;
        int k = i >> 3, ch = i & 7;
        uint32_t dsto = (uint32_t)(k*32 + ((ch ^ (k&7)) << 2))*4u;
        CP_A16(sb_k + dsto, Kg + (size_t)k*HD_ + ch*8);
        CP_A16(sb_v + dsto, Vg + (size_t)k*HD_ + ch*8);
    }
    CP_COMMIT();
    CP_WAIT(1);            // Q ready (KV0 may be in flight)
    __syncthreads();

    // hoist Q A-frags (warp w owns rows 16w..16w+15)
    int r = wid * 16;
    uint32_t qa[4][4];
#pragma unroll
    for (int ks = 0; ks < 4; ks++) {
        int cl  = ((2*ks    ) ^ lr)*4 + lc;
        int chh = ((2*ks + 1) ^ lr)*4 + lc;
        qa[ks][0] = sm_q[(r+lr  )*32 + cl ];
        qa[ks][1] = sm_q[(r+lr+8)*32 + cl ];
        qa[ks][2] = sm_q[(r+lr  )*32 + chh];
        qa[ks][3] = sm_q[(r+lr+8)*32 + chh];
    }

    // lane constants for ldmatrix V addressing
    int krow  = ((lane >> 3) & 1)*8 + (lane & 7);   // row within 16-k chunk
    int clnof = lane >> 4;                          // 0/1: chunk pair selector
    int swz7  = lane & 7;                           // = krow&7

    float ov[8][4] = {};
    float m0 = -1e30f, m1 = -1e30f, l0 = 0.f, l1 = 0.f;

    for (int kt = 0; kt < 13; kt++) {
        __syncthreads();        // (A) all warps done with compute(kt-1) -> stage (kt+1)&1 free

        // issue KV(kt+1) as one group
        if (kt < 12) {
            int kn = (kt+1)*64;
            uint32_t st = (uint32_t)((kt+1) & 1)*8192u;
#pragma unroll
            for (int e = 0; e < 4; e++) {
                int i = e*128 + t;
                int k = i >> 3, ch = i & 7;
                int kg = kn + k;
                uint32_t dsto = (uint32_t)(k*32 + ((ch ^ (k&7)) << 2))*4u;
                const unsigned short* srcK = Kg + (size_t)(kg < S_ ? kg : S_-1)*HD_ + ch*8;
                const unsigned short* srcV = Vg + (size_t)(kg < S_ ? kg : S_-1)*HD_ + ch*8;
                CP_A16P(sb_k + st + dsto, srcK, kg < S_);
                CP_A16P(sb_v + st + dsto, srcV, kg < S_);
            }
        }
        CP_COMMIT();
        CP_WAIT(1);             // KV(kt) complete
        __syncthreads();        // (B) KV(kt) visible

        const uint32_t* Ks_ = sm_k + (kt & 1)*2048;
        uint32_t vb = sb_v + (uint32_t)(kt & 1)*8192u;

        // ---- scores: S[16q x 64k] per warp (log2 units) ----
        float sc[8][4] = {};
#pragma unroll
        for (int ks = 0; ks < 4; ks++) {
            int cl  = ((2*ks    ) ^ lr)*4 + lc;
            int chh = ((2*ks + 1) ^ lr)*4 + lc;
#pragma unroll
            for (int j = 0; j < 8; j++) {
                uint32_t b0 = Ks_[(8*j+lr)*32 + cl ];
                uint32_t b1 = Ks_[(8*j+lr)*32 + chh];
                mma_f16(sc[j], qa[ks], b0, b1);
            }
        }

        // ---- masking: only last k-tile ----
        if (kt == 12) {
#pragma unroll
            for (int j = 0; j < 8; j++) {
                int col = 768 + 8*j + 2*lc;
                if (col     >= S_) { sc[j][0] = -1e30f; sc[j][2] = -1e30f; }
                if (col + 1 >= S_) { sc[j][1] = -1e30f; sc[j][3] = -1e30f; }
            }
        }

        // ---- online softmax, log2 domain ----
        float mx0 = -1e30f, mx1 = -1e30f;
#pragma unroll
        for (int j = 0; j < 8; j++) {
            mx0 = fmaxf(mx0, fmaxf(sc[j][0], sc[j][1]));
            mx1 = fmaxf(mx1, fmaxf(sc[j][2], sc[j][3]));
        }
        mx0 = fmaxf(mx0, __shfl_xor_sync(0xffffffffu, mx0, 1));
        mx0 = fmaxf(mx0, __shfl_xor_sync(0xffffffffu, mx0, 2));
        mx1 = fmaxf(mx1, __shfl_xor_sync(0xffffffffu, mx1, 1));
        mx1 = fmaxf(mx1, __shfl_xor_sync(0xffffffffu, mx1, 2));
        float mn0 = fmaxf(m0, mx0), mn1 = fmaxf(m1, mx1);
        float a0  = ex2f(m0 - mn0), a1 = ex2f(m1 - mn1);
        float rs0 = 0.f, rs1 = 0.f;
#pragma unroll
        for (int j = 0; j < 8; j++) {
            sc[j][0] = ex2f(sc[j][0] - mn0); rs0 += sc[j][0];
            sc[j][1] = ex2f(sc[j][1] - mn0); rs0 += sc[j][1];
            sc[j][2] = ex2f(sc[j][2] - mn1); rs1 += sc[j][2];
            sc[j][3] = ex2f(sc[j][3] - mn1); rs1 += sc[j][3];
        }
        rs0 += __shfl_xor_sync(0xffffffffu, rs0, 1);
        rs0 += __shfl_xor_sync(0xffffffffu, rs0, 2);
        rs1 += __shfl_xor_sync(0xffffffffu, rs1, 1);
        rs1 += __shfl_xor_sync(0xffffffffu, rs1, 2);
        l0 = l0*a0 + rs0;  l1 = l1*a1 + rs1;
        m0 = mn0;          m1 = mn1;
#pragma unroll
        for (int j = 0; j < 8; j++) {
            ov[j][0] *= a0; ov[j][1] *= a0;
            ov[j][2] *= a1; ov[j][3] *= a1;
        }

        // ---- PV: O += P @ V, P direct from registers (QK acc == PV A-frag) --
#pragma unroll
        for (int ks = 0; ks < 4; ks++) {
            uint32_t pa[4];
            pa[0] = pack_h2(sc[2*ks  ][0], sc[2*ks  ][1]);
            pa[1] = pack_h2(sc[2*ks  ][2], sc[2*ks  ][3]);
            pa[2] = pack_h2(sc[2*ks+1][0], sc[2*ks+1][1]);
            pa[3] = pack_h2(sc[2*ks+1][2], sc[2*ks+1][3]);
            uint32_t vrow = vb + (uint32_t)((16*ks + krow)*32)*4u;
#pragma unroll
            for (int jp = 0; jp < 4; jp++) {
                int chv = (2*jp + clnof) ^ swz7;
                uint32_t v0, v1, v2, v3;
                ldsm4t(v0, v1, v2, v3, vrow + (uint32_t)(chv << 4));
                mma_f16(ov[2*jp    ], pa, v0, v1);
                mma_f16(ov[2*jp + 1], pa, v2, v3);
            }
        }
    }

    float inv0 = 1.0f / l0, inv1 = 1.0f / l1;
    int qq0 = q0 + r + lr, qq1 = qq0 + 8;
#pragma unroll
    for (int j = 0; j < 8; j++) {
        int d = 8*j + 2*lc;
        if (qq0 < S_) {
            float2 o2 = make_float2(ov[j][0]*inv0, ov[j][1]*inv0);
            *(float2*)&Op[(size_t)qq0*HD_ + d] = o2;
        }
        if (qq1 < S_) {
            float2 o2 = make_float2(ov[j][2]*inv1, ov[j][3]*inv1);
            *(float2*)&Op[(size_t)qq1*HD_ + d] = o2;
        }
    }
}

// ---------------------------------------------------------------------------
extern "C" void kernel_launch(void* const* d_in, const int* in_sizes, int n_in,
                              void* d_out, int out_size) {
    // metadata order: x1, h1, w1, x2, h2, w2, dw_w, bn_gamma, bn_beta, pw_w, pw_b, lin_w
    const float* x1  = (const float*)d_in[0];
    const float* x2  = (const float*)d_in[3];
    const float* dww = (const float*)d_in[6];
    const float* gam = (const float*)d_in[7];
    const float* bet = (const float*)d_in[8];
    const float* pw  = (const float*)d_in[9];
    const float* pwb = (const float*)d_in[10];
    const float* lin = (const float*)d_in[11];
    float* out = (float*)d_out;

    cudaFuncSetAttribute(gemm_kernel, cudaFuncAttributeMaxDynamicSharedMemorySize, 66048);
    cudaFuncSetAttribute(attn_kernel, cudaFuncAttributeMaxDynamicSharedMemorySize, 40960);

    dw_kernel   <<<dim3(14, 16, 3), 384>>>(x1, x2, dww);
    fold_kernel <<<dim3(6, 6, 9), 256>>>(pw, lin, gam, bet, pwb);
    gemm_kernel <<<dim3(3, 98, 9), 256, 66048>>>();
    attn_kernel <<<dim3(13, 96, 3), 128, 40960>>>(out);
}